// round 7
// baseline (speedup 1.0000x reference)
#include <cuda_runtime.h>
#include <cuda_bf16.h>
#include <cstdint>
#include <math.h>

#define M_ 1024
#define N_ 1024
#define D_ 2048

// ================= helpers =================
__device__ __forceinline__ uint32_t smem_to_u32(const void* p) {
    uint32_t a;
    asm("{ .reg .u64 t; cvta.to.shared.u64 t, %1; cvt.u32.u64 %0, t; }" : "=r"(a) : "l"(p));
    return a;
}
#define SMEM_SWIZZLE_128B(b) ((b) ^ (((b) >> 3) & 0x70))

#define LDSM_X4(r, a) \
    asm volatile("ldmatrix.sync.aligned.m8n8.x4.shared.b16 {%0,%1,%2,%3}, [%4];" \
        : "=r"((r)[0]), "=r"((r)[1]), "=r"((r)[2]), "=r"((r)[3]) : "r"(a))

__device__ __forceinline__ void mma16816(float* c, const uint32_t* a, uint32_t b0, uint32_t b1) {
    asm volatile("mma.sync.aligned.m16n8k16.row.col.f32.bf16.bf16.f32 "
        "{%0,%1,%2,%3}, {%4,%5,%6,%7}, {%8,%9}, {%0,%1,%2,%3};"
        : "+f"(c[0]), "+f"(c[1]), "+f"(c[2]), "+f"(c[3])
        : "r"(a[0]), "r"(a[1]), "r"(a[2]), "r"(a[3]), "r"(b0), "r"(b1));
}

// ================= scratch =================
__device__ __nv_bfloat16 g_vph[M_ * D_], g_vpl[M_ * D_];
__device__ __nv_bfloat16 g_uch[N_ * D_], g_ucl[N_ * D_];
__device__ __nv_bfloat16 g_ucTh[D_ * N_], g_ucTl[D_ * N_];
__device__ __nv_bfloat16 g_upTh[D_ * M_], g_upTl[D_ * M_];
__device__ __nv_bfloat16 g_Sah[M_ * N_], g_Sal[M_ * N_];
__device__ __nv_bfloat16 g_SbTh[N_ * M_], g_SbTl[N_ * M_];
__device__ float g_Sp[4 * M_ * N_];   // GEMM1 split-K partials
__device__ float g_S[M_ * N_];
__device__ float g_rp[M_], g_rc[N_];
__device__ float g_pmax[8 * N_], g_psum[8 * N_];
__device__ float g_cmax[N_], g_cinv[N_];
__device__ float g_aa[N_ * D_], g_ab[N_ * D_];
__device__ float g_part[N_];

__device__ __forceinline__ void split_store(__nv_bfloat16* oh, __nv_bfloat16* ol,
                                            size_t off, float4 v) {
    __nv_bfloat16 h0 = __float2bfloat16(v.x), h1 = __float2bfloat16(v.y);
    __nv_bfloat16 h2 = __float2bfloat16(v.z), h3 = __float2bfloat16(v.w);
    __nv_bfloat16 l0 = __float2bfloat16(v.x - __bfloat162float(h0));
    __nv_bfloat16 l1 = __float2bfloat16(v.y - __bfloat162float(h1));
    __nv_bfloat16 l2 = __float2bfloat16(v.z - __bfloat162float(h2));
    __nv_bfloat16 l3 = __float2bfloat16(v.w - __bfloat162float(h3));
    *(__nv_bfloat162*)(oh + off)     = __halves2bfloat162(h0, h1);
    *(__nv_bfloat162*)(oh + off + 2) = __halves2bfloat162(h2, h3);
    *(__nv_bfloat162*)(ol + off)     = __halves2bfloat162(l0, l1);
    *(__nv_bfloat162*)(ol + off + 2) = __halves2bfloat162(l2, l3);
}

__device__ __forceinline__ float block_reduce_sum_256(float v, float* red) {
    int t = threadIdx.x;
    red[t] = v;
    __syncthreads();
    #pragma unroll
    for (int s = 128; s > 0; s >>= 1) {
        if (t < s) red[t] += red[t + s];
        __syncthreads();
    }
    return red[0];
}

// ================= K0: rp, rc, vp hi/lo, uc hi/lo =================
__global__ void rv_kernel(const float* __restrict__ up, const float* __restrict__ uc,
                          const float* __restrict__ wa) {
    __shared__ float red[256];
    int row = blockIdx.x, t = threadIdx.x;
    if (row < M_) {
        const float* a = up + (size_t)row * D_;
        const float* w1 = wa;
        const float* w3 = wa + 2 * D_;
        float s = 0.f;
        for (int k = t * 4; k < D_; k += 1024) {
            float4 av = *(const float4*)(a + k);
            float4 w1v = *(const float4*)(w1 + k);
            float4 w3v = *(const float4*)(w3 + k);
            s += av.x * w1v.x + av.y * w1v.y + av.z * w1v.z + av.w * w1v.w;
            float4 vv = make_float4(av.x * w3v.x, av.y * w3v.y, av.z * w3v.z, av.w * w3v.w);
            split_store(g_vph, g_vpl, (size_t)row * D_ + k, vv);
        }
        float tot = block_reduce_sum_256(s, red);
        if (t == 0) g_rp[row] = tot;
    } else {
        int r2 = row - M_;
        const float* a = uc + (size_t)r2 * D_;
        const float* w2 = wa + D_;
        float s = 0.f;
        for (int k = t * 4; k < D_; k += 1024) {
            float4 av = *(const float4*)(a + k);
            float4 w2v = *(const float4*)(w2 + k);
            s += av.x * w2v.x + av.y * w2v.y + av.z * w2v.z + av.w * w2v.w;
            split_store(g_uch, g_ucl, (size_t)r2 * D_ + k, av);
        }
        float tot = block_reduce_sum_256(s, red);
        if (t == 0) g_rc[r2] = tot;
    }
}

// ================= transpose + split convert =================
__global__ void transpose_split(const float* __restrict__ in, int R, int C,
                                __nv_bfloat16* __restrict__ oh, __nv_bfloat16* __restrict__ ol) {
    __shared__ float t[32][33];
    int tx = threadIdx.x, ty = threadIdx.y;
    int r0 = blockIdx.y * 32, c0 = blockIdx.x * 32;
    #pragma unroll
    for (int j = 0; j < 4; j++)
        t[ty + j * 8][tx] = in[(size_t)(r0 + ty + j * 8) * C + c0 + tx];
    __syncthreads();
    #pragma unroll
    for (int j = 0; j < 4; j++) {
        int c = c0 + ty + j * 8;
        float v = t[tx][ty + j * 8];
        __nv_bfloat16 h = __float2bfloat16(v);
        __nv_bfloat16 l = __float2bfloat16(v - __bfloat162float(h));
        oh[(size_t)c * R + r0 + tx] = h;
        ol[(size_t)c * R + r0 + tx] = l;
    }
}

__global__ void transpose_softmax_split(const float* __restrict__ S) {
    __shared__ float t[32][33];
    int tx = threadIdx.x, ty = threadIdx.y;
    int r0 = blockIdx.y * 32, c0 = blockIdx.x * 32;
    float cm = g_cmax[c0 + tx], ci = g_cinv[c0 + tx];
    #pragma unroll
    for (int j = 0; j < 4; j++) {
        float v = S[(size_t)(r0 + ty + j * 8) * N_ + c0 + tx];
        t[ty + j * 8][tx] = __expf(v - cm) * ci;
    }
    __syncthreads();
    #pragma unroll
    for (int j = 0; j < 4; j++) {
        int c = c0 + ty + j * 8;
        float v = t[tx][ty + j * 8];
        __nv_bfloat16 h = __float2bfloat16(v);
        __nv_bfloat16 l = __float2bfloat16(v - __bfloat162float(h));
        g_SbTh[(size_t)c * M_ + r0 + tx] = h;
        g_SbTl[(size_t)c * M_ + r0 + tx] = l;
    }
}

// ================= col softmax stats =================
__global__ void col_stats_part(const float* __restrict__ S) {
    int tx = threadIdx.x, ty = threadIdx.y;
    int c = blockIdx.x * 128 + tx;
    int r0 = blockIdx.y * 128;
    float mx = -INFINITY, sm = 0.f;
    for (int r = ty; r < 128; r += 4) {
        float v = S[(size_t)(r0 + r) * N_ + c];
        float mn = fmaxf(mx, v);
        sm = sm * __expf(mx - mn) + __expf(v - mn);
        mx = mn;
    }
    __shared__ float m2[4][128], s2[4][128];
    m2[ty][tx] = mx; s2[ty][tx] = sm;
    __syncthreads();
    if (ty == 0) {
        float m = m2[0][tx], s = s2[0][tx];
        #pragma unroll
        for (int k = 1; k < 4; k++) {
            float mm = m2[k][tx], ss = s2[k][tx];
            float mn = fmaxf(m, mm);
            s = s * __expf(m - mn) + ss * __expf(mm - mn);
            m = mn;
        }
        g_pmax[blockIdx.y * N_ + c] = m;
        g_psum[blockIdx.y * N_ + c] = s;
    }
}

__global__ void col_stats_combine() {
    int c = blockIdx.x * 256 + threadIdx.x;
    float m = g_pmax[c], s = g_psum[c];
    #pragma unroll
    for (int k = 1; k < 8; k++) {
        float mm = g_pmax[k * N_ + c], ss = g_psum[k * N_ + c];
        float mn = fmaxf(m, mm);
        s = s * __expf(m - mn) + ss * __expf(mm - mn);
        m = mn;
    }
    g_cmax[c] = m;
    g_cinv[c] = 1.0f / s;
}

// ================= merge split-K partials + bias + row softmax =================
__global__ void merge_rowsoftmax() {
    __shared__ float red[256];
    int row = blockIdx.x, t = threadIdx.x;
    float rpv = g_rp[row];
    int j = t * 4;
    float4 a = *(const float4*)(g_Sp + (size_t)row * N_ + j);
    float4 b = *(const float4*)(g_Sp + (size_t)M_ * N_ + (size_t)row * N_ + j);
    float4 c = *(const float4*)(g_Sp + 2 * (size_t)M_ * N_ + (size_t)row * N_ + j);
    float4 d = *(const float4*)(g_Sp + 3 * (size_t)M_ * N_ + (size_t)row * N_ + j);
    float4 rc4 = *(const float4*)(g_rc + j);
    float4 o;
    o.x = a.x + b.x + c.x + d.x + rpv + rc4.x;
    o.y = a.y + b.y + c.y + d.y + rpv + rc4.y;
    o.z = a.z + b.z + c.z + d.z + rpv + rc4.z;
    o.w = a.w + b.w + c.w + d.w + rpv + rc4.w;
    *(float4*)(g_S + (size_t)row * N_ + j) = o;

    float mx = fmaxf(fmaxf(o.x, o.y), fmaxf(o.z, o.w));
    red[t] = mx;
    __syncthreads();
    #pragma unroll
    for (int s = 128; s > 0; s >>= 1) {
        if (t < s) red[t] = fmaxf(red[t], red[t + s]);
        __syncthreads();
    }
    mx = red[0];
    __syncthreads();
    float e0 = __expf(o.x - mx), e1 = __expf(o.y - mx);
    float e2 = __expf(o.z - mx), e3 = __expf(o.w - mx);
    float sum = block_reduce_sum_256(e0 + e1 + e2 + e3, red);
    float inv = 1.0f / sum;
    split_store(g_Sah, g_Sal, (size_t)row * N_ + j,
                make_float4(e0 * inv, e1 * inv, e2 * inv, e3 * inv));
}

// ================= mma.sync GEMM core: 128x128 tile, 3-stage, 1 sync/chunk =================
#define NSTG 3
#define TILE_B 16384
#define SMEM_GEMM (2 * NSTG * TILE_B)    // 98304 per CTA; 2 CTAs/SM = 192KB

__device__ __forceinline__ void cp_tile(uint32_t sdst, const __nv_bfloat16* src,
                                        int row0, int ld, int k0, int tid) {
    const char* gb = (const char*)(src + (size_t)row0 * ld + k0);
    size_t rb = (size_t)ld * 2;
    #pragma unroll
    for (int it = 0; it < 4; it++) {
        int idx = tid + it * 256;
        int r = idx >> 3;
        int cb = (idx & 7) << 4;
        const void* g = gb + (size_t)r * rb + cb;
        uint32_t s = sdst + SMEM_SWIZZLE_128B(r * 128 + cb);
        asm volatile("cp.async.cg.shared.global [%0], [%1], 16;" :: "r"(s), "l"(g));
    }
}

__device__ __forceinline__ void chunk_src(int ci, int nkc,
    const __nv_bfloat16* Ahi, const __nv_bfloat16* Alo,
    const __nv_bfloat16* Bhi, const __nv_bfloat16* Blo,
    const __nv_bfloat16** As, const __nv_bfloat16** Bs, int* kk)
{
    int p = ci / nkc;
    int kc = ci - p * nkc;
    *kk = kc << 6;
    *As = (p == 1) ? Alo : Ahi;
    *Bs = (p == 2) ? Blo : Bhi;
}

__device__ __forceinline__ void gemm_core(
    const __nv_bfloat16* __restrict__ Ahi, const __nv_bfloat16* __restrict__ Alo,
    const __nv_bfloat16* __restrict__ Bhi, const __nv_bfloat16* __restrict__ Blo,
    float* __restrict__ C, int ldc, int Kdim, int c0, int ncl, int i0, int j0)
{
    extern __shared__ __align__(1024) char smem[];
    uint32_t sb = smem_to_u32(smem);
    const int tid = threadIdx.x;
    const int wid = tid >> 5, lane = tid & 31;
    const int wm = wid & 1, wn = wid >> 1;      // warp tile 64x32 in 2x4 grid

    float acc[4][4][4];
    #pragma unroll
    for (int a = 0; a < 4; a++)
        #pragma unroll
        for (int b = 0; b < 4; b++)
            #pragma unroll
            for (int c = 0; c < 4; c++) acc[a][b][c] = 0.f;

    // per-thread ldmatrix offsets, swizzled once; k-step applied via XOR
    uint32_t cA = (uint32_t)((wm * 64 + (lane & 15)) << 7) + ((lane >> 4) << 4);
    cA ^= ((cA >> 3) & 0x70);
    uint32_t rowB = (lane & 7) + ((lane >> 4) << 3);
    uint32_t cB = (uint32_t)((wn * 32 + rowB) << 7) + (((lane >> 3) & 1) << 4);
    cB ^= ((cB >> 3) & 0x70);

    const int nkc = Kdim >> 6;

    #define STG_A(s) (sb + (s) * TILE_B)
    #define STG_B(s) (sb + NSTG * TILE_B + (s) * TILE_B)

    {
        const __nv_bfloat16 *As, *Bs; int kk;
        chunk_src(c0, nkc, Ahi, Alo, Bhi, Blo, &As, &Bs, &kk);
        cp_tile(STG_A(0), As, i0, Kdim, kk, tid);
        cp_tile(STG_B(0), Bs, j0, Kdim, kk, tid);
        asm volatile("cp.async.commit_group;" ::: "memory");
        chunk_src(c0 + 1, nkc, Ahi, Alo, Bhi, Blo, &As, &Bs, &kk);
        cp_tile(STG_A(1), As, i0, Kdim, kk, tid);
        cp_tile(STG_B(1), Bs, j0, Kdim, kk, tid);
        asm volatile("cp.async.commit_group;" ::: "memory");
    }

    for (int li = 0; li < ncl; li++) {
        int s = li % NSTG;
        asm volatile("cp.async.wait_group 1;" ::: "memory");
        __syncthreads();
        // prefetch chunk li+2 into stage (li+2)%3 == (li-1)%3 — the stage every
        // warp finished reading before this iteration's barrier. Loads fly
        // during the MMA block below.
        if (li + 2 < ncl) {
            const __nv_bfloat16 *As, *Bs; int kk;
            chunk_src(c0 + li + 2, nkc, Ahi, Alo, Bhi, Blo, &As, &Bs, &kk);
            cp_tile(STG_A((li + 2) % NSTG), As, i0, Kdim, kk, tid);
            cp_tile(STG_B((li + 2) % NSTG), Bs, j0, Kdim, kk, tid);
        }
        asm volatile("cp.async.commit_group;" ::: "memory");

        uint32_t aBase = STG_A(s) + cA;
        uint32_t bBase = STG_B(s) + cB;
        #pragma unroll
        for (int ks = 0; ks < 4; ks++) {
            uint32_t afr[4][4], bfr[2][4];
            #pragma unroll
            for (int mt = 0; mt < 4; mt++)
                LDSM_X4(afr[mt], (aBase + mt * 2048) ^ (ks << 5));
            #pragma unroll
            for (int p = 0; p < 2; p++)
                LDSM_X4(bfr[p], (bBase + p * 2048) ^ (ks << 5));
            #pragma unroll
            for (int mt = 0; mt < 4; mt++) {
                #pragma unroll
                for (int p = 0; p < 2; p++) {
                    mma16816(acc[mt][p * 2 + 0], afr[mt], bfr[p][0], bfr[p][1]);
                    mma16816(acc[mt][p * 2 + 1], afr[mt], bfr[p][2], bfr[p][3]);
                }
            }
        }
    }

    const int gid = lane >> 2, tig = lane & 3;
    #pragma unroll
    for (int mt = 0; mt < 4; mt++) {
        int gi = i0 + wm * 64 + mt * 16 + gid;
        #pragma unroll
        for (int nt = 0; nt < 4; nt++) {
            int gj = j0 + wn * 32 + nt * 8 + tig * 2;
            *(float2*)(C + (size_t)gi * ldc + gj) = make_float2(acc[mt][nt][0], acc[mt][nt][1]);
            *(float2*)(C + (size_t)(gi + 8) * ldc + gj) = make_float2(acc[mt][nt][2], acc[mt][nt][3]);
        }
    }
    #undef STG_A
    #undef STG_B
}

// GEMM1: split-K x4, partial outputs
__global__ __launch_bounds__(256, 2) void gemm_splitk(
    const __nv_bfloat16* __restrict__ Ahi, const __nv_bfloat16* __restrict__ Alo,
    const __nv_bfloat16* __restrict__ Bhi, const __nv_bfloat16* __restrict__ Blo,
    float* __restrict__ Cp)
{
    int z = blockIdx.z;
    const int nch = 3 * (D_ >> 6);     // 96
    const int q = nch / 4;             // 24
    gemm_core(Ahi, Alo, Bhi, Blo, Cp + (size_t)z * M_ * N_, N_, D_,
              z * q, q, blockIdx.y * 128, blockIdx.x * 128);
}

// GEMM2+3 fused: z picks operand set
__global__ __launch_bounds__(256, 2) void gemm_dual(
    const __nv_bfloat16* __restrict__ A0h, const __nv_bfloat16* __restrict__ A0l,
    const __nv_bfloat16* __restrict__ B0h, const __nv_bfloat16* __restrict__ B0l,
    float* __restrict__ C0,
    const __nv_bfloat16* __restrict__ A1h, const __nv_bfloat16* __restrict__ A1l,
    const __nv_bfloat16* __restrict__ B1h, const __nv_bfloat16* __restrict__ B1l,
    float* __restrict__ C1)
{
    int z = blockIdx.z;
    const __nv_bfloat16* Ah = z ? A1h : A0h;
    const __nv_bfloat16* Al = z ? A1l : A0l;
    const __nv_bfloat16* Bh = z ? B1h : B0h;
    const __nv_bfloat16* Bl = z ? B1l : B0l;
    float* C = z ? C1 : C0;
    const int nch = 3 * (N_ >> 6);     // 48
    gemm_core(Ah, Al, Bh, Bl, C, D_, N_, 0, nch, blockIdx.y * 128, blockIdx.x * 128);
}

// ================= FFN =================
__global__ void ffn_partial(const float* __restrict__ up, const float* __restrict__ uc,
                            const float* __restrict__ W) {
    __shared__ float red[256];
    int i = blockIdx.x, t = threadIdx.x;
    const float* Wi = W + (size_t)i * 4 * D_;
    const float* upi = up + (size_t)i * D_;
    const float* uci = uc + (size_t)i * D_;
    const float* aai = g_aa + (size_t)i * D_;
    const float* abi = g_ab + (size_t)i * D_;
    float s = 0.f;
    for (int k = t * 4; k < D_; k += 1024) {
        float4 u  = *(const float4*)(upi + k);
        float4 aa = *(const float4*)(aai + k);
        float4 ab = *(const float4*)(abi + k);
        float4 cc = *(const float4*)(uci + k);
        float4 w0 = *(const float4*)(Wi + k);
        float4 w1 = *(const float4*)(Wi + D_ + k);
        float4 w2 = *(const float4*)(Wi + 2 * D_ + k);
        float4 w3 = *(const float4*)(Wi + 3 * D_ + k);
        s += u.x * w0.x + u.y * w0.y + u.z * w0.z + u.w * w0.w;
        s += aa.x * w1.x + aa.y * w1.y + aa.z * w1.z + aa.w * w1.w;
        s += u.x * aa.x * w2.x + u.y * aa.y * w2.y + u.z * aa.z * w2.z + u.w * aa.w * w2.w;
        s += cc.x * ab.x * w3.x + cc.y * ab.y * w3.y + cc.z * ab.z * w3.z + cc.w * ab.w * w3.w;
    }
    float tot = block_reduce_sum_256(s, red);
    if (t == 0) g_part[i] = tot;
}

__global__ void ffn_final(const float* __restrict__ b, float* __restrict__ out) {
    __shared__ float red[256];
    int t = threadIdx.x;
    float s = 0.f;
    for (int i = t; i < N_; i += 256) s += g_part[i];
    float tot = block_reduce_sum_256(s, red);
    if (t == 0) out[0] = fmaxf(tot + b[0], 0.f);
}

// ================= launch =================
extern "C" void kernel_launch(void* const* d_in, const int* in_sizes, int n_in,
                              void* d_out, int out_size) {
    const float* u_p   = (const float*)d_in[0];
    const float* u_c   = (const float*)d_in[1];
    const float* w_a   = (const float*)d_in[2];
    const float* ffn_w = (const float*)d_in[3];
    const float* ffn_b = (const float*)d_in[4];
    float* out = (float*)d_out;

    cudaFuncSetAttribute(gemm_splitk, cudaFuncAttributeMaxDynamicSharedMemorySize, SMEM_GEMM);
    cudaFuncSetAttribute(gemm_dual,   cudaFuncAttributeMaxDynamicSharedMemorySize, SMEM_GEMM);

    float *S, *Sp, *aa, *ab;
    __nv_bfloat16 *vph, *vpl, *uch, *ucl, *ucTh, *ucTl, *upTh, *upTl, *Sah, *Sal, *SbTh, *SbTl;
    cudaGetSymbolAddress((void**)&S, g_S);
    cudaGetSymbolAddress((void**)&Sp, g_Sp);
    cudaGetSymbolAddress((void**)&aa, g_aa);
    cudaGetSymbolAddress((void**)&ab, g_ab);
    cudaGetSymbolAddress((void**)&vph, g_vph);
    cudaGetSymbolAddress((void**)&vpl, g_vpl);
    cudaGetSymbolAddress((void**)&uch, g_uch);
    cudaGetSymbolAddress((void**)&ucl, g_ucl);
    cudaGetSymbolAddress((void**)&ucTh, g_ucTh);
    cudaGetSymbolAddress((void**)&ucTl, g_ucTl);
    cudaGetSymbolAddress((void**)&upTh, g_upTh);
    cudaGetSymbolAddress((void**)&upTl, g_upTl);
    cudaGetSymbolAddress((void**)&Sah, g_Sah);
    cudaGetSymbolAddress((void**)&Sal, g_Sal);
    cudaGetSymbolAddress((void**)&SbTh, g_SbTh);
    cudaGetSymbolAddress((void**)&SbTl, g_SbTl);

    // K0: rp, rc, vp hi/lo, uc hi/lo
    rv_kernel<<<M_ + N_, 256>>>(u_p, u_c, w_a);

    // transposed splits for GEMM2/3 B operands
    transpose_split<<<dim3(D_ / 32, N_ / 32), dim3(32, 8)>>>(u_c, N_, D_, ucTh, ucTl);
    transpose_split<<<dim3(D_ / 32, M_ / 32), dim3(32, 8)>>>(u_p, M_, D_, upTh, upTl);

    // GEMM1: S partials (split-K x4), then merge + bias + row softmax
    gemm_splitk<<<dim3(N_ / 128, M_ / 128, 4), 256, SMEM_GEMM>>>(vph, vpl, uch, ucl, Sp);
    merge_rowsoftmax<<<M_, 256>>>();

    // col softmax stats + transposed Sb
    col_stats_part<<<dim3(N_ / 128, 8), dim3(128, 4)>>>(S);
    col_stats_combine<<<N_ / 256, 256>>>();
    transpose_softmax_split<<<dim3(N_ / 32, M_ / 32), dim3(32, 8)>>>(S);

    // GEMM2 + GEMM3 fused
    gemm_dual<<<dim3(D_ / 128, M_ / 128, 2), 256, SMEM_GEMM>>>(
        Sah, Sal, ucTh, ucTl, aa,
        SbTh, SbTl, upTh, upTl, ab);

    // FFN
    ffn_partial<<<N_, 256>>>(u_p, u_c, ffn_w);
    ffn_final<<<1, 256>>>(ffn_b, out);
}

// round 8
// speedup vs baseline: 1.3151x; 1.3151x over previous
#include <cuda_runtime.h>
#include <cuda_bf16.h>
#include <cstdint>
#include <math.h>

#define M_ 1024
#define N_ 1024
#define D_ 2048

// ================= helpers =================
__device__ __forceinline__ uint32_t smem_to_u32(const void* p) {
    uint32_t a;
    asm("{ .reg .u64 t; cvta.to.shared.u64 t, %1; cvt.u32.u64 %0, t; }" : "=r"(a) : "l"(p));
    return a;
}
#define SMEM_SWIZZLE_128B(b) ((b) ^ (((b) >> 3) & 0x70))

#define LDSM_X4(r, a) \
    asm volatile("ldmatrix.sync.aligned.m8n8.x4.shared.b16 {%0,%1,%2,%3}, [%4];" \
        : "=r"((r)[0]), "=r"((r)[1]), "=r"((r)[2]), "=r"((r)[3]) : "r"(a))

__device__ __forceinline__ void mma_tf32(float* c, const uint32_t* a, uint32_t b0, uint32_t b1) {
    asm volatile("mma.sync.aligned.m16n8k8.row.col.f32.tf32.tf32.f32 "
        "{%0,%1,%2,%3}, {%4,%5,%6,%7}, {%8,%9}, {%0,%1,%2,%3};"
        : "+f"(c[0]), "+f"(c[1]), "+f"(c[2]), "+f"(c[3])
        : "r"(a[0]), "r"(a[1]), "r"(a[2]), "r"(a[3]), "r"(b0), "r"(b1));
}

__device__ __forceinline__ float tf32r(float x) {
    uint32_t r;
    asm("cvt.rna.tf32.f32 %0, %1;" : "=r"(r) : "f"(x));
    return __uint_as_float(r);
}

// ================= scratch (fp32, tf32-rounded operands) =================
__device__ float g_vp32[M_ * D_];     // tf32(u_p * w3)          [M][D]
__device__ float g_uc32[N_ * D_];     // tf32(u_c)               [N][D]
__device__ float g_ucT32[D_ * N_];    // tf32(u_c^T)             [D][N]
__device__ float g_upT32[D_ * M_];    // tf32(u_p^T)             [D][M]
__device__ float g_Sa32[M_ * N_];     // tf32(row softmax)       [M][N]
__device__ float g_SbT32[N_ * M_];    // tf32(col softmax ^T)    [N][M]
__device__ float g_Sp[4 * M_ * N_];   // GEMM1 split-K partials
__device__ float g_S[M_ * N_];
__device__ float g_rp[M_], g_rc[N_];
__device__ float g_pmax[8 * N_], g_psum[8 * N_];
__device__ float g_cmax[N_], g_cinv[N_];
__device__ float g_aa[N_ * D_], g_ab[N_ * D_];
__device__ float g_part[N_];

__device__ __forceinline__ float block_reduce_sum_256(float v, float* red) {
    int t = threadIdx.x;
    red[t] = v;
    __syncthreads();
    #pragma unroll
    for (int s = 128; s > 0; s >>= 1) {
        if (t < s) red[t] += red[t + s];
        __syncthreads();
    }
    return red[0];
}

// ================= K0: rp, rc, vp32, uc32 =================
__global__ void rv_kernel(const float* __restrict__ up, const float* __restrict__ uc,
                          const float* __restrict__ wa) {
    __shared__ float red[256];
    int row = blockIdx.x, t = threadIdx.x;
    if (row < M_) {
        const float* a = up + (size_t)row * D_;
        const float* w1 = wa;
        const float* w3 = wa + 2 * D_;
        float s = 0.f;
        for (int k = t * 4; k < D_; k += 1024) {
            float4 av = *(const float4*)(a + k);
            float4 w1v = *(const float4*)(w1 + k);
            float4 w3v = *(const float4*)(w3 + k);
            s += av.x * w1v.x + av.y * w1v.y + av.z * w1v.z + av.w * w1v.w;
            float4 vv = make_float4(tf32r(av.x * w3v.x), tf32r(av.y * w3v.y),
                                    tf32r(av.z * w3v.z), tf32r(av.w * w3v.w));
            *(float4*)(g_vp32 + (size_t)row * D_ + k) = vv;
        }
        float tot = block_reduce_sum_256(s, red);
        if (t == 0) g_rp[row] = tot;
    } else {
        int r2 = row - M_;
        const float* a = uc + (size_t)r2 * D_;
        const float* w2 = wa + D_;
        float s = 0.f;
        for (int k = t * 4; k < D_; k += 1024) {
            float4 av = *(const float4*)(a + k);
            float4 w2v = *(const float4*)(w2 + k);
            s += av.x * w2v.x + av.y * w2v.y + av.z * w2v.z + av.w * w2v.w;
            float4 cv = make_float4(tf32r(av.x), tf32r(av.y), tf32r(av.z), tf32r(av.w));
            *(float4*)(g_uc32 + (size_t)r2 * D_ + k) = cv;
        }
        float tot = block_reduce_sum_256(s, red);
        if (t == 0) g_rc[r2] = tot;
    }
}

// ================= transpose + tf32 round =================
__global__ void transpose32(const float* __restrict__ in, int R, int C,
                            float* __restrict__ outT) {
    __shared__ float t[32][33];
    int tx = threadIdx.x, ty = threadIdx.y;
    int r0 = blockIdx.y * 32, c0 = blockIdx.x * 32;
    #pragma unroll
    for (int j = 0; j < 4; j++)
        t[ty + j * 8][tx] = in[(size_t)(r0 + ty + j * 8) * C + c0 + tx];
    __syncthreads();
    #pragma unroll
    for (int j = 0; j < 4; j++) {
        int c = c0 + ty + j * 8;
        outT[(size_t)c * R + r0 + tx] = tf32r(t[tx][ty + j * 8]);
    }
}

__global__ void transpose_softmax32(const float* __restrict__ S) {
    __shared__ float t[32][33];
    int tx = threadIdx.x, ty = threadIdx.y;
    int r0 = blockIdx.y * 32, c0 = blockIdx.x * 32;
    float cm = g_cmax[c0 + tx], ci = g_cinv[c0 + tx];
    #pragma unroll
    for (int j = 0; j < 4; j++) {
        float v = S[(size_t)(r0 + ty + j * 8) * N_ + c0 + tx];
        t[ty + j * 8][tx] = __expf(v - cm) * ci;
    }
    __syncthreads();
    #pragma unroll
    for (int j = 0; j < 4; j++) {
        int c = c0 + ty + j * 8;
        g_SbT32[(size_t)c * M_ + r0 + tx] = tf32r(t[tx][ty + j * 8]);
    }
}

// ================= col softmax stats =================
__global__ void col_stats_part(const float* __restrict__ S) {
    int tx = threadIdx.x, ty = threadIdx.y;
    int c = blockIdx.x * 128 + tx;
    int r0 = blockIdx.y * 128;
    float mx = -INFINITY, sm = 0.f;
    for (int r = ty; r < 128; r += 4) {
        float v = S[(size_t)(r0 + r) * N_ + c];
        float mn = fmaxf(mx, v);
        sm = sm * __expf(mx - mn) + __expf(v - mn);
        mx = mn;
    }
    __shared__ float m2[4][128], s2[4][128];
    m2[ty][tx] = mx; s2[ty][tx] = sm;
    __syncthreads();
    if (ty == 0) {
        float m = m2[0][tx], s = s2[0][tx];
        #pragma unroll
        for (int k = 1; k < 4; k++) {
            float mm = m2[k][tx], ss = s2[k][tx];
            float mn = fmaxf(m, mm);
            s = s * __expf(m - mn) + ss * __expf(mm - mn);
            m = mn;
        }
        g_pmax[blockIdx.y * N_ + c] = m;
        g_psum[blockIdx.y * N_ + c] = s;
    }
}

__global__ void col_stats_combine() {
    int c = blockIdx.x * 256 + threadIdx.x;
    float m = g_pmax[c], s = g_psum[c];
    #pragma unroll
    for (int k = 1; k < 8; k++) {
        float mm = g_pmax[k * N_ + c], ss = g_psum[k * N_ + c];
        float mn = fmaxf(m, mm);
        s = s * __expf(m - mn) + ss * __expf(mm - mn);
        m = mn;
    }
    g_cmax[c] = m;
    g_cinv[c] = 1.0f / s;
}

// ================= merge split-K partials + bias + row softmax =================
__global__ void merge_rowsoftmax() {
    __shared__ float red[256];
    int row = blockIdx.x, t = threadIdx.x;
    float rpv = g_rp[row];
    int j = t * 4;
    float4 a = *(const float4*)(g_Sp + (size_t)row * N_ + j);
    float4 b = *(const float4*)(g_Sp + (size_t)M_ * N_ + (size_t)row * N_ + j);
    float4 c = *(const float4*)(g_Sp + 2 * (size_t)M_ * N_ + (size_t)row * N_ + j);
    float4 d = *(const float4*)(g_Sp + 3 * (size_t)M_ * N_ + (size_t)row * N_ + j);
    float4 rc4 = *(const float4*)(g_rc + j);
    float4 o;
    o.x = a.x + b.x + c.x + d.x + rpv + rc4.x;
    o.y = a.y + b.y + c.y + d.y + rpv + rc4.y;
    o.z = a.z + b.z + c.z + d.z + rpv + rc4.z;
    o.w = a.w + b.w + c.w + d.w + rpv + rc4.w;
    *(float4*)(g_S + (size_t)row * N_ + j) = o;

    float mx = fmaxf(fmaxf(o.x, o.y), fmaxf(o.z, o.w));
    red[t] = mx;
    __syncthreads();
    #pragma unroll
    for (int s = 128; s > 0; s >>= 1) {
        if (t < s) red[t] = fmaxf(red[t], red[t + s]);
        __syncthreads();
    }
    mx = red[0];
    __syncthreads();
    float e0 = __expf(o.x - mx), e1 = __expf(o.y - mx);
    float e2 = __expf(o.z - mx), e3 = __expf(o.w - mx);
    float sum = block_reduce_sum_256(e0 + e1 + e2 + e3, red);
    float inv = 1.0f / sum;
    float4 p = make_float4(tf32r(e0 * inv), tf32r(e1 * inv), tf32r(e2 * inv), tf32r(e3 * inv));
    *(float4*)(g_Sa32 + (size_t)row * N_ + j) = p;
}

// ================= tf32 mma GEMM core: 128x128 tile, K-chunk 32, 3-stage =================
#define NSTG 3
#define TILE_SZ 16384                         // 128 rows x 32 floats (128B) per stage
#define SMEM_GEMM (2 * NSTG * TILE_SZ)        // 98304 per CTA; 2 CTAs/SM

__device__ __forceinline__ void cp_tile32(uint32_t sdst, const float* src,
                                          int row0, int ld, int k0, int tid) {
    const char* gb = (const char*)(src + (size_t)row0 * ld + k0);
    size_t rb = (size_t)ld * 4;
    #pragma unroll
    for (int it = 0; it < 4; it++) {
        int idx = tid + it * 256;
        int r = idx >> 3;
        int cb = (idx & 7) << 4;
        const void* g = gb + (size_t)r * rb + cb;
        uint32_t s = sdst + SMEM_SWIZZLE_128B(r * 128 + cb);
        asm volatile("cp.async.cg.shared.global [%0], [%1], 16;" :: "r"(s), "l"(g));
    }
}

__device__ __forceinline__ void gemm_core(
    const float* __restrict__ A, const float* __restrict__ B,
    float* __restrict__ C, int ldc, int Kdim, int c0, int ncl, int i0, int j0)
{
    extern __shared__ __align__(1024) char smem[];
    uint32_t sb = smem_to_u32(smem);
    const int tid = threadIdx.x;
    const int wid = tid >> 5, lane = tid & 31;
    const int wm = wid & 1, wn = wid >> 1;      // warp tile 64x32 in 2x4 grid

    float acc[4][4][4];
    #pragma unroll
    for (int a = 0; a < 4; a++)
        #pragma unroll
        for (int b = 0; b < 4; b++)
            #pragma unroll
            for (int c = 0; c < 4; c++) acc[a][b][c] = 0.f;

    // tf32 ldmatrix addressing (fp32 elements; 8x4-float tiles via b16 ldmatrix)
    // A: q=lane>>3 -> tiles {a0:(r0-7,c0-3), a1:(r8-15,c0-3), a2:(r0-7,c4-7), a3:(r8-15,c4-7)}
    uint32_t rowA = (uint32_t)(wm * 64 + ((lane >> 3) & 1) * 8 + (lane & 7));
    uint32_t cA = rowA * 128 + ((lane >> 4) & 1) * 16;
    cA ^= ((cA >> 3) & 0x70);
    // B: tiles {b0(nt0), b1(nt0), b0(nt1), b1(nt1)} per x4; +2048 covers next 2 ntiles
    uint32_t rowB = (uint32_t)(wn * 32 + ((lane >> 4) & 1) * 8 + (lane & 7));
    uint32_t cB = rowB * 128 + ((lane >> 3) & 1) * 16;
    cB ^= ((cB >> 3) & 0x70);

    #define STG_A(s) (sb + (s) * TILE_SZ)
    #define STG_B(s) (sb + NSTG * TILE_SZ + (s) * TILE_SZ)

    cp_tile32(STG_A(0), A, i0, Kdim, (c0) * 32, tid);
    cp_tile32(STG_B(0), B, j0, Kdim, (c0) * 32, tid);
    asm volatile("cp.async.commit_group;" ::: "memory");
    cp_tile32(STG_A(1), A, i0, Kdim, (c0 + 1) * 32, tid);
    cp_tile32(STG_B(1), B, j0, Kdim, (c0 + 1) * 32, tid);
    asm volatile("cp.async.commit_group;" ::: "memory");

    for (int li = 0; li < ncl; li++) {
        int s = li % NSTG;
        asm volatile("cp.async.wait_group 1;" ::: "memory");
        __syncthreads();
        // prefetch into stage (li+2)%3 == (li-1)%3 (already drained before this barrier)
        if (li + 2 < ncl) {
            cp_tile32(STG_A((li + 2) % NSTG), A, i0, Kdim, (c0 + li + 2) * 32, tid);
            cp_tile32(STG_B((li + 2) % NSTG), B, j0, Kdim, (c0 + li + 2) * 32, tid);
        }
        asm volatile("cp.async.commit_group;" ::: "memory");

        uint32_t aBase = STG_A(s) + cA;
        uint32_t bBase = STG_B(s) + cB;
        #pragma unroll
        for (int ks = 0; ks < 4; ks++) {          // 4 x k8 per K32 chunk
            uint32_t afr[4][4], bfr[2][4];
            #pragma unroll
            for (int mt = 0; mt < 4; mt++)
                LDSM_X4(afr[mt], (aBase + mt * 2048) ^ (ks << 5));
            #pragma unroll
            for (int p = 0; p < 2; p++)
                LDSM_X4(bfr[p], (bBase + p * 2048) ^ (ks << 5));
            #pragma unroll
            for (int mt = 0; mt < 4; mt++) {
                #pragma unroll
                for (int p = 0; p < 2; p++) {
                    mma_tf32(acc[mt][p * 2 + 0], afr[mt], bfr[p][0], bfr[p][1]);
                    mma_tf32(acc[mt][p * 2 + 1], afr[mt], bfr[p][2], bfr[p][3]);
                }
            }
        }
    }

    const int gid = lane >> 2, tig = lane & 3;
    #pragma unroll
    for (int mt = 0; mt < 4; mt++) {
        int gi = i0 + wm * 64 + mt * 16 + gid;
        #pragma unroll
        for (int nt = 0; nt < 4; nt++) {
            int gj = j0 + wn * 32 + nt * 8 + tig * 2;
            *(float2*)(C + (size_t)gi * ldc + gj) = make_float2(acc[mt][nt][0], acc[mt][nt][1]);
            *(float2*)(C + (size_t)(gi + 8) * ldc + gj) = make_float2(acc[mt][nt][2], acc[mt][nt][3]);
        }
    }
    #undef STG_A
    #undef STG_B
}

// GEMM1: S partials = vp32 @ uc32^T, split-K x4
__global__ __launch_bounds__(256, 2) void gemm_splitk(
    const float* __restrict__ A, const float* __restrict__ B, float* __restrict__ Cp)
{
    int z = blockIdx.z;
    const int nkc = D_ / 32;           // 64 chunks
    const int q = nkc / 4;             // 16 per split
    gemm_core(A, B, Cp + (size_t)z * M_ * N_, N_, D_,
              z * q, q, blockIdx.y * 128, blockIdx.x * 128);
}

// GEMM2+3 fused: z picks operand set
__global__ __launch_bounds__(256, 2) void gemm_dual(
    const float* __restrict__ A0, const float* __restrict__ B0, float* __restrict__ C0,
    const float* __restrict__ A1, const float* __restrict__ B1, float* __restrict__ C1)
{
    int z = blockIdx.z;
    const float* A = z ? A1 : A0;
    const float* B = z ? B1 : B0;
    float* C = z ? C1 : C0;
    gemm_core(A, B, C, D_, N_, 0, N_ / 32, blockIdx.y * 128, blockIdx.x * 128);
}

// ================= FFN =================
__global__ void ffn_partial(const float* __restrict__ up, const float* __restrict__ uc,
                            const float* __restrict__ W) {
    __shared__ float red[256];
    int i = blockIdx.x, t = threadIdx.x;
    const float* Wi = W + (size_t)i * 4 * D_;
    const float* upi = up + (size_t)i * D_;
    const float* uci = uc + (size_t)i * D_;
    const float* aai = g_aa + (size_t)i * D_;
    const float* abi = g_ab + (size_t)i * D_;
    float s = 0.f;
    for (int k = t * 4; k < D_; k += 1024) {
        float4 u  = *(const float4*)(upi + k);
        float4 aa = *(const float4*)(aai + k);
        float4 ab = *(const float4*)(abi + k);
        float4 cc = *(const float4*)(uci + k);
        float4 w0 = *(const float4*)(Wi + k);
        float4 w1 = *(const float4*)(Wi + D_ + k);
        float4 w2 = *(const float4*)(Wi + 2 * D_ + k);
        float4 w3 = *(const float4*)(Wi + 3 * D_ + k);
        s += u.x * w0.x + u.y * w0.y + u.z * w0.z + u.w * w0.w;
        s += aa.x * w1.x + aa.y * w1.y + aa.z * w1.z + aa.w * w1.w;
        s += u.x * aa.x * w2.x + u.y * aa.y * w2.y + u.z * aa.z * w2.z + u.w * aa.w * w2.w;
        s += cc.x * ab.x * w3.x + cc.y * ab.y * w3.y + cc.z * ab.z * w3.z + cc.w * ab.w * w3.w;
    }
    float tot = block_reduce_sum_256(s, red);
    if (t == 0) g_part[i] = tot;
}

__global__ void ffn_final(const float* __restrict__ b, float* __restrict__ out) {
    __shared__ float red[256];
    int t = threadIdx.x;
    float s = 0.f;
    for (int i = t; i < N_; i += 256) s += g_part[i];
    float tot = block_reduce_sum_256(s, red);
    if (t == 0) out[0] = fmaxf(tot + b[0], 0.f);
}

// ================= launch =================
extern "C" void kernel_launch(void* const* d_in, const int* in_sizes, int n_in,
                              void* d_out, int out_size) {
    const float* u_p   = (const float*)d_in[0];
    const float* u_c   = (const float*)d_in[1];
    const float* w_a   = (const float*)d_in[2];
    const float* ffn_w = (const float*)d_in[3];
    const float* ffn_b = (const float*)d_in[4];
    float* out = (float*)d_out;

    cudaFuncSetAttribute(gemm_splitk, cudaFuncAttributeMaxDynamicSharedMemorySize, SMEM_GEMM);
    cudaFuncSetAttribute(gemm_dual,   cudaFuncAttributeMaxDynamicSharedMemorySize, SMEM_GEMM);

    float *S, *Sp, *aa, *ab, *vp32, *uc32, *ucT32, *upT32, *Sa32, *SbT32;
    cudaGetSymbolAddress((void**)&S, g_S);
    cudaGetSymbolAddress((void**)&Sp, g_Sp);
    cudaGetSymbolAddress((void**)&aa, g_aa);
    cudaGetSymbolAddress((void**)&ab, g_ab);
    cudaGetSymbolAddress((void**)&vp32, g_vp32);
    cudaGetSymbolAddress((void**)&uc32, g_uc32);
    cudaGetSymbolAddress((void**)&ucT32, g_ucT32);
    cudaGetSymbolAddress((void**)&upT32, g_upT32);
    cudaGetSymbolAddress((void**)&Sa32, g_Sa32);
    cudaGetSymbolAddress((void**)&SbT32, g_SbT32);

    // K0: rp, rc, vp32, uc32
    rv_kernel<<<M_ + N_, 256>>>(u_p, u_c, w_a);

    // transposed tf32 operands for GEMM2/3 B
    transpose32<<<dim3(D_ / 32, N_ / 32), dim3(32, 8)>>>(u_c, N_, D_, ucT32);
    transpose32<<<dim3(D_ / 32, M_ / 32), dim3(32, 8)>>>(u_p, M_, D_, upT32);

    // GEMM1: S partials (split-K x4), then merge + bias + row softmax
    gemm_splitk<<<dim3(N_ / 128, M_ / 128, 4), 256, SMEM_GEMM>>>(vp32, uc32, Sp);
    merge_rowsoftmax<<<M_, 256>>>();

    // col softmax stats + transposed Sb
    col_stats_part<<<dim3(N_ / 128, 8), dim3(128, 4)>>>(S);
    col_stats_combine<<<N_ / 256, 256>>>();
    transpose_softmax32<<<dim3(N_ / 32, M_ / 32), dim3(32, 8)>>>(S);

    // GEMM2 + GEMM3 fused: aa = Sa@uc, ab = Sb^T@up
    gemm_dual<<<dim3(D_ / 128, M_ / 128, 2), 256, SMEM_GEMM>>>(
        Sa32, ucT32, aa,
        SbT32, upT32, ab);

    // FFN
    ffn_partial<<<N_, 256>>>(u_p, u_c, ffn_w);
    ffn_final<<<1, 256>>>(ffn_b, out);
}

// round 9
// speedup vs baseline: 1.9333x; 1.4701x over previous
#include <cuda_runtime.h>
#include <cuda_fp16.h>
#include <cstdint>
#include <math.h>

#define M_ 1024
#define N_ 1024
#define D_ 2048

// ================= helpers =================
__device__ __forceinline__ uint32_t smem_to_u32(const void* p) {
    uint32_t a;
    asm("{ .reg .u64 t; cvta.to.shared.u64 t, %1; cvt.u32.u64 %0, t; }" : "=r"(a) : "l"(p));
    return a;
}
#define SMEM_SWIZZLE_128B(b) ((b) ^ (((b) >> 3) & 0x70))

#define LDSM_X4(r, a) \
    asm volatile("ldmatrix.sync.aligned.m8n8.x4.shared.b16 {%0,%1,%2,%3}, [%4];" \
        : "=r"((r)[0]), "=r"((r)[1]), "=r"((r)[2]), "=r"((r)[3]) : "r"(a))

__device__ __forceinline__ void mma_f16(float* c, const uint32_t* a, uint32_t b0, uint32_t b1) {
    asm volatile("mma.sync.aligned.m16n8k16.row.col.f32.f16.f16.f32 "
        "{%0,%1,%2,%3}, {%4,%5,%6,%7}, {%8,%9}, {%0,%1,%2,%3};"
        : "+f"(c[0]), "+f"(c[1]), "+f"(c[2]), "+f"(c[3])
        : "r"(a[0]), "r"(a[1]), "r"(a[2]), "r"(a[3]), "r"(b0), "r"(b1));
}

// ================= scratch =================
__device__ __half g_vp16[M_ * D_];    // h(u_p * w3)   [M][D]
__device__ __half g_uc16[N_ * D_];    // h(u_c)        [N][D]
__device__ __half g_ucT16[D_ * N_];   // h(u_c^T)      [D][N]
__device__ __half g_upT16[D_ * M_];   // h(u_p^T)      [D][M]
__device__ __half g_Sa16[M_ * N_];    // h(row softmax)[M][N]
__device__ __half g_SbT16[N_ * M_];   // h(col softmax^T) [N][M]
__device__ float g_Sp[4 * M_ * N_];   // GEMM1 split-K partials
__device__ float g_S[M_ * N_];
__device__ float g_rp[M_], g_rc[N_];
__device__ float g_pmax[8 * N_], g_psum[8 * N_];
__device__ float g_cmax[N_], g_cinv[N_];
__device__ float g_part[M_];          // FFN term1 per row (u_p . W0)
__device__ float g_ctapart[256];      // FFN partials from dual CTAs

__device__ __forceinline__ float block_reduce_sum_256(float v, float* red) {
    int t = threadIdx.x;
    __syncthreads();
    red[t] = v;
    __syncthreads();
    #pragma unroll
    for (int s = 128; s > 0; s >>= 1) {
        if (t < s) red[t] += red[t + s];
        __syncthreads();
    }
    return red[0];
}

__device__ __forceinline__ void store_h4(__half* dst, size_t off, float4 v) {
    __half2 lo = __halves2half2(__float2half_rn(v.x), __float2half_rn(v.y));
    __half2 hi = __halves2half2(__float2half_rn(v.z), __float2half_rn(v.w));
    *(__half2*)(dst + off)     = lo;
    *(__half2*)(dst + off + 2) = hi;
}

// ================= K0: rp, rc, term1, vp16, uc16 =================
__global__ void rv_kernel(const float* __restrict__ up, const float* __restrict__ uc,
                          const float* __restrict__ wa, const float* __restrict__ W) {
    __shared__ float red[256];
    int row = blockIdx.x, t = threadIdx.x;
    if (row < M_) {
        const float* a = up + (size_t)row * D_;
        const float* w1 = wa;
        const float* w3 = wa + 2 * D_;
        const float* W0 = W + (size_t)row * 4 * D_;
        float s = 0.f, s1 = 0.f;
        for (int k = t * 4; k < D_; k += 1024) {
            float4 av = *(const float4*)(a + k);
            float4 w1v = *(const float4*)(w1 + k);
            float4 w3v = *(const float4*)(w3 + k);
            float4 W0v = *(const float4*)(W0 + k);
            s += av.x * w1v.x + av.y * w1v.y + av.z * w1v.z + av.w * w1v.w;
            s1 += av.x * W0v.x + av.y * W0v.y + av.z * W0v.z + av.w * W0v.w;
            store_h4(g_vp16, (size_t)row * D_ + k,
                     make_float4(av.x * w3v.x, av.y * w3v.y, av.z * w3v.z, av.w * w3v.w));
        }
        float tot = block_reduce_sum_256(s, red);
        if (t == 0) g_rp[row] = tot;
        float tot1 = block_reduce_sum_256(s1, red);
        if (t == 0) g_part[row] = tot1;
    } else {
        int r2 = row - M_;
        const float* a = uc + (size_t)r2 * D_;
        const float* w2 = wa + D_;
        float s = 0.f;
        for (int k = t * 4; k < D_; k += 1024) {
            float4 av = *(const float4*)(a + k);
            float4 w2v = *(const float4*)(w2 + k);
            s += av.x * w2v.x + av.y * w2v.y + av.z * w2v.z + av.w * w2v.w;
            store_h4(g_uc16, (size_t)r2 * D_ + k, av);
        }
        float tot = block_reduce_sum_256(s, red);
        if (t == 0) g_rc[r2] = tot;
    }
}

// ================= transpose + fp16 convert =================
__global__ void transpose16(const float* __restrict__ in, int R, int C,
                            __half* __restrict__ outT) {
    __shared__ float t[32][33];
    int tx = threadIdx.x, ty = threadIdx.y;
    int r0 = blockIdx.y * 32, c0 = blockIdx.x * 32;
    #pragma unroll
    for (int j = 0; j < 4; j++)
        t[ty + j * 8][tx] = in[(size_t)(r0 + ty + j * 8) * C + c0 + tx];
    __syncthreads();
    #pragma unroll
    for (int j = 0; j < 4; j++) {
        int c = c0 + ty + j * 8;
        outT[(size_t)c * R + r0 + tx] = __float2half_rn(t[tx][ty + j * 8]);
    }
}

__global__ void transpose_softmax16(const float* __restrict__ S) {
    __shared__ float t[32][33];
    int tx = threadIdx.x, ty = threadIdx.y;
    int r0 = blockIdx.y * 32, c0 = blockIdx.x * 32;
    float cm = g_cmax[c0 + tx], ci = g_cinv[c0 + tx];
    #pragma unroll
    for (int j = 0; j < 4; j++) {
        float v = S[(size_t)(r0 + ty + j * 8) * N_ + c0 + tx];
        t[ty + j * 8][tx] = __expf(v - cm) * ci;
    }
    __syncthreads();
    #pragma unroll
    for (int j = 0; j < 4; j++) {
        int c = c0 + ty + j * 8;
        g_SbT16[(size_t)c * M_ + r0 + tx] = __float2half_rn(t[tx][ty + j * 8]);
    }
}

// ================= col softmax stats =================
__global__ void col_stats_part(const float* __restrict__ S) {
    int tx = threadIdx.x, ty = threadIdx.y;
    int c = blockIdx.x * 128 + tx;
    int r0 = blockIdx.y * 128;
    float mx = -INFINITY, sm = 0.f;
    for (int r = ty; r < 128; r += 4) {
        float v = S[(size_t)(r0 + r) * N_ + c];
        float mn = fmaxf(mx, v);
        sm = sm * __expf(mx - mn) + __expf(v - mn);
        mx = mn;
    }
    __shared__ float m2[4][128], s2[4][128];
    m2[ty][tx] = mx; s2[ty][tx] = sm;
    __syncthreads();
    if (ty == 0) {
        float m = m2[0][tx], s = s2[0][tx];
        #pragma unroll
        for (int k = 1; k < 4; k++) {
            float mm = m2[k][tx], ss = s2[k][tx];
            float mn = fmaxf(m, mm);
            s = s * __expf(m - mn) + ss * __expf(mm - mn);
            m = mn;
        }
        g_pmax[blockIdx.y * N_ + c] = m;
        g_psum[blockIdx.y * N_ + c] = s;
    }
}

__global__ void col_stats_combine() {
    int c = blockIdx.x * 256 + threadIdx.x;
    float m = g_pmax[c], s = g_psum[c];
    #pragma unroll
    for (int k = 1; k < 8; k++) {
        float mm = g_pmax[k * N_ + c], ss = g_psum[k * N_ + c];
        float mn = fmaxf(m, mm);
        s = s * __expf(m - mn) + ss * __expf(mm - mn);
        m = mn;
    }
    g_cmax[c] = m;
    g_cinv[c] = 1.0f / s;
}

// ================= merge split-K partials + bias + row softmax =================
__global__ void merge_rowsoftmax() {
    __shared__ float red[256];
    int row = blockIdx.x, t = threadIdx.x;
    float rpv = g_rp[row];
    int j = t * 4;
    float4 a = *(const float4*)(g_Sp + (size_t)row * N_ + j);
    float4 b = *(const float4*)(g_Sp + (size_t)M_ * N_ + (size_t)row * N_ + j);
    float4 c = *(const float4*)(g_Sp + 2 * (size_t)M_ * N_ + (size_t)row * N_ + j);
    float4 d = *(const float4*)(g_Sp + 3 * (size_t)M_ * N_ + (size_t)row * N_ + j);
    float4 rc4 = *(const float4*)(g_rc + j);
    float4 o;
    o.x = a.x + b.x + c.x + d.x + rpv + rc4.x;
    o.y = a.y + b.y + c.y + d.y + rpv + rc4.y;
    o.z = a.z + b.z + c.z + d.z + rpv + rc4.z;
    o.w = a.w + b.w + c.w + d.w + rpv + rc4.w;
    *(float4*)(g_S + (size_t)row * N_ + j) = o;

    float mx = fmaxf(fmaxf(o.x, o.y), fmaxf(o.z, o.w));
    __syncthreads();
    red[t] = mx;
    __syncthreads();
    #pragma unroll
    for (int s = 128; s > 0; s >>= 1) {
        if (t < s) red[t] = fmaxf(red[t], red[t + s]);
        __syncthreads();
    }
    mx = red[0];
    float e0 = __expf(o.x - mx), e1 = __expf(o.y - mx);
    float e2 = __expf(o.z - mx), e3 = __expf(o.w - mx);
    float sum = block_reduce_sum_256(e0 + e1 + e2 + e3, red);
    float inv = 1.0f / sum;
    store_h4(g_Sa16, (size_t)row * N_ + j,
             make_float4(e0 * inv, e1 * inv, e2 * inv, e3 * inv));
}

// ================= fp16 mma GEMM core: 128x128 tile, K-chunk 64, 3-stage =================
#define NSTG 3
#define TILE_B 16384
#define SMEM_GEMM (2 * NSTG * TILE_B)   // 96 KB per CTA; 2 CTAs/SM

__device__ __forceinline__ void cp_tile(uint32_t sdst, const __half* src,
                                        int row0, int ld, int k0, int tid) {
    const char* gb = (const char*)(src + (size_t)row0 * ld + k0);
    size_t rb = (size_t)ld * 2;
    #pragma unroll
    for (int it = 0; it < 4; it++) {
        int idx = tid + it * 256;
        int r = idx >> 3;
        int cb = (idx & 7) << 4;
        const void* g = gb + (size_t)r * rb + cb;
        uint32_t s = sdst + SMEM_SWIZZLE_128B(r * 128 + cb);
        asm volatile("cp.async.cg.shared.global [%0], [%1], 16;" :: "r"(s), "l"(g));
    }
}

// fills acc; warp layout: 2x4 warp grid, warp tile 64x32
__device__ __forceinline__ void gemm_compute(
    const __half* __restrict__ A, const __half* __restrict__ B,
    int Kdim, int c0, int ncl, int i0, int j0,
    float (&acc)[4][4][4])
{
    extern __shared__ __align__(1024) char smem[];
    uint32_t sb = smem_to_u32(smem);
    const int tid = threadIdx.x;
    const int wid = tid >> 5, lane = tid & 31;
    const int wm = wid & 1, wn = wid >> 1;

    #pragma unroll
    for (int a = 0; a < 4; a++)
        #pragma unroll
        for (int b = 0; b < 4; b++)
            #pragma unroll
            for (int c = 0; c < 4; c++) acc[a][b][c] = 0.f;

    uint32_t cA = (uint32_t)((wm * 64 + (lane & 15)) << 7) + ((lane >> 4) << 4);
    cA ^= ((cA >> 3) & 0x70);
    uint32_t rowB = (lane & 7) + ((lane >> 4) << 3);
    uint32_t cB = (uint32_t)((wn * 32 + rowB) << 7) + (((lane >> 3) & 1) << 4);
    cB ^= ((cB >> 3) & 0x70);

    #define STG_A(s) (sb + (s) * TILE_B)
    #define STG_B(s) (sb + NSTG * TILE_B + (s) * TILE_B)

    cp_tile(STG_A(0), A, i0, Kdim, (c0) * 64, tid);
    cp_tile(STG_B(0), B, j0, Kdim, (c0) * 64, tid);
    asm volatile("cp.async.commit_group;" ::: "memory");
    cp_tile(STG_A(1), A, i0, Kdim, (c0 + 1) * 64, tid);
    cp_tile(STG_B(1), B, j0, Kdim, (c0 + 1) * 64, tid);
    asm volatile("cp.async.commit_group;" ::: "memory");

    for (int li = 0; li < ncl; li++) {
        int s = li % NSTG;
        asm volatile("cp.async.wait_group 1;" ::: "memory");
        __syncthreads();
        if (li + 2 < ncl) {
            cp_tile(STG_A((li + 2) % NSTG), A, i0, Kdim, (c0 + li + 2) * 64, tid);
            cp_tile(STG_B((li + 2) % NSTG), B, j0, Kdim, (c0 + li + 2) * 64, tid);
        }
        asm volatile("cp.async.commit_group;" ::: "memory");

        uint32_t aBase = STG_A(s) + cA;
        uint32_t bBase = STG_B(s) + cB;
        #pragma unroll
        for (int ks = 0; ks < 4; ks++) {      // 4 x k16 per K64 chunk
            uint32_t afr[4][4], bfr[2][4];
            #pragma unroll
            for (int mt = 0; mt < 4; mt++)
                LDSM_X4(afr[mt], (aBase + mt * 2048) ^ (ks << 5));
            #pragma unroll
            for (int p = 0; p < 2; p++)
                LDSM_X4(bfr[p], (bBase + p * 2048) ^ (ks << 5));
            #pragma unroll
            for (int mt = 0; mt < 4; mt++) {
                #pragma unroll
                for (int p = 0; p < 2; p++) {
                    mma_f16(acc[mt][p * 2 + 0], afr[mt], bfr[p][0], bfr[p][1]);
                    mma_f16(acc[mt][p * 2 + 1], afr[mt], bfr[p][2], bfr[p][3]);
                }
            }
        }
    }
    #undef STG_A
    #undef STG_B
}

// GEMM1: S partials = vp16 @ uc16^T, split-K x4
__global__ __launch_bounds__(256, 2) void gemm_splitk(
    const __half* __restrict__ A, const __half* __restrict__ B, float* __restrict__ Cp)
{
    int z = blockIdx.z;
    const int q = (D_ / 64) / 4;       // 8 chunks per split
    int i0 = blockIdx.y * 128, j0 = blockIdx.x * 128;
    float acc[4][4][4];
    gemm_compute(A, B, D_, z * q, q, i0, j0, acc);

    const int lane = threadIdx.x & 31, wid = threadIdx.x >> 5;
    const int wm = wid & 1, wn = wid >> 1;
    const int gid = lane >> 2, tig = lane & 3;
    float* C = Cp + (size_t)z * M_ * N_;
    #pragma unroll
    for (int mt = 0; mt < 4; mt++) {
        int gi = i0 + wm * 64 + mt * 16 + gid;
        #pragma unroll
        for (int nt = 0; nt < 4; nt++) {
            int gj = j0 + wn * 32 + nt * 8 + tig * 2;
            *(float2*)(C + (size_t)gi * N_ + gj) = make_float2(acc[mt][nt][0], acc[mt][nt][1]);
            *(float2*)(C + (size_t)(gi + 8) * N_ + gj) = make_float2(acc[mt][nt][2], acc[mt][nt][3]);
        }
    }
}

// GEMM2+3 fused with FFN epilogue: z=0 computes aa tiles -> (aa.W1 + up*aa.W2);
// z=1 computes ab tiles -> (uc*ab.W3). Partials per CTA; nothing else to gmem.
__global__ __launch_bounds__(256, 2) void gemm_dual_ffn(
    const __half* __restrict__ Sa, const __half* __restrict__ ucT,
    const __half* __restrict__ SbT, const __half* __restrict__ upT,
    const float* __restrict__ up, const float* __restrict__ uc,
    const float* __restrict__ W)
{
    __shared__ float red[256];
    int z = blockIdx.z;
    const __half* A = z ? SbT : Sa;
    const __half* B = z ? upT : ucT;
    int i0 = blockIdx.y * 128, j0 = blockIdx.x * 128;   // i: token row, j: D col
    float acc[4][4][4];
    gemm_compute(A, B, N_, 0, N_ / 64, i0, j0, acc);

    const int lane = threadIdx.x & 31, wid = threadIdx.x >> 5;
    const int wm = wid & 1, wn = wid >> 1;
    const int gid = lane >> 2, tig = lane & 3;
    const float* uin = z ? uc : up;
    float part = 0.f;
    #pragma unroll
    for (int mt = 0; mt < 4; mt++) {
        int gi0 = i0 + wm * 64 + mt * 16 + gid;
        #pragma unroll
        for (int r = 0; r < 2; r++) {
            int gi = gi0 + r * 8;
            const float* Wr = W + (size_t)gi * 4 * D_;
            #pragma unroll
            for (int nt = 0; nt < 4; nt++) {
                int gj = j0 + wn * 32 + nt * 8 + tig * 2;
                float a0 = acc[mt][nt][r * 2 + 0];
                float a1 = acc[mt][nt][r * 2 + 1];
                float2 uv = *(const float2*)(uin + (size_t)gi * D_ + gj);
                if (z == 0) {
                    float2 w1 = *(const float2*)(Wr + D_ + gj);
                    float2 w2 = *(const float2*)(Wr + 2 * D_ + gj);
                    part += a0 * (w1.x + uv.x * w2.x) + a1 * (w1.y + uv.y * w2.y);
                } else {
                    float2 w3 = *(const float2*)(Wr + 3 * D_ + gj);
                    part += a0 * uv.x * w3.x + a1 * uv.y * w3.y;
                }
            }
        }
    }
    float tot = block_reduce_sum_256(part, red);
    if (threadIdx.x == 0)
        g_ctapart[z * 128 + blockIdx.y * 16 + blockIdx.x] = tot;
}

// ================= final scalar =================
__global__ void ffn_final(const float* __restrict__ b, float* __restrict__ out) {
    __shared__ float red[256];
    int t = threadIdx.x;
    float s = 0.f;
    for (int i = t; i < M_; i += 256) s += g_part[i];
    if (t < 256) s += g_ctapart[t];
    float tot = block_reduce_sum_256(s, red);
    if (t == 0) out[0] = fmaxf(tot + b[0], 0.f);
}

// ================= launch =================
extern "C" void kernel_launch(void* const* d_in, const int* in_sizes, int n_in,
                              void* d_out, int out_size) {
    const float* u_p   = (const float*)d_in[0];
    const float* u_c   = (const float*)d_in[1];
    const float* w_a   = (const float*)d_in[2];
    const float* ffn_w = (const float*)d_in[3];
    const float* ffn_b = (const float*)d_in[4];
    float* out = (float*)d_out;

    cudaFuncSetAttribute(gemm_splitk,   cudaFuncAttributeMaxDynamicSharedMemorySize, SMEM_GEMM);
    cudaFuncSetAttribute(gemm_dual_ffn, cudaFuncAttributeMaxDynamicSharedMemorySize, SMEM_GEMM);

    float *S, *Sp;
    __half *vp16, *uc16, *ucT16, *upT16, *Sa16, *SbT16;
    cudaGetSymbolAddress((void**)&S, g_S);
    cudaGetSymbolAddress((void**)&Sp, g_Sp);
    cudaGetSymbolAddress((void**)&vp16, g_vp16);
    cudaGetSymbolAddress((void**)&uc16, g_uc16);
    cudaGetSymbolAddress((void**)&ucT16, g_ucT16);
    cudaGetSymbolAddress((void**)&upT16, g_upT16);
    cudaGetSymbolAddress((void**)&Sa16, g_Sa16);
    cudaGetSymbolAddress((void**)&SbT16, g_SbT16);

    // K0: rp, rc, FFN term1, vp16, uc16
    rv_kernel<<<M_ + N_, 256>>>(u_p, u_c, w_a, ffn_w);

    // transposed fp16 operands for GEMM2/3 B
    transpose16<<<dim3(D_ / 32, N_ / 32), dim3(32, 8)>>>(u_c, N_, D_, ucT16);
    transpose16<<<dim3(D_ / 32, M_ / 32), dim3(32, 8)>>>(u_p, M_, D_, upT16);

    // GEMM1: S partials (split-K x4), then merge + bias + row softmax
    gemm_splitk<<<dim3(N_ / 128, M_ / 128, 4), 256, SMEM_GEMM>>>(vp16, uc16, Sp);
    merge_rowsoftmax<<<M_, 256>>>();

    // col softmax stats + transposed Sb
    col_stats_part<<<dim3(N_ / 128, 8), dim3(128, 4)>>>(S);
    col_stats_combine<<<N_ / 256, 256>>>();
    transpose_softmax16<<<dim3(N_ / 32, M_ / 32), dim3(32, 8)>>>(S);

    // GEMM2 + GEMM3 + FFN fused
    gemm_dual_ffn<<<dim3(D_ / 128, M_ / 128, 2), 256, SMEM_GEMM>>>(
        Sa16, ucT16, SbT16, upT16, u_p, u_c, ffn_w);

    // final scalar
    ffn_final<<<1, 256>>>(ffn_b, out);
}

// round 10
// speedup vs baseline: 1.9766x; 1.0224x over previous
#include <cuda_runtime.h>
#include <cuda_fp16.h>
#include <cstdint>
#include <math.h>

#define M_ 1024
#define N_ 1024
#define D_ 2048

// ================= helpers =================
__device__ __forceinline__ uint32_t smem_to_u32(const void* p) {
    uint32_t a;
    asm("{ .reg .u64 t; cvta.to.shared.u64 t, %1; cvt.u32.u64 %0, t; }" : "=r"(a) : "l"(p));
    return a;
}
#define SMEM_SWIZZLE_128B(b) ((b) ^ (((b) >> 3) & 0x70))

#define LDSM_X4(r, a) \
    asm volatile("ldmatrix.sync.aligned.m8n8.x4.shared.b16 {%0,%1,%2,%3}, [%4];" \
        : "=r"((r)[0]), "=r"((r)[1]), "=r"((r)[2]), "=r"((r)[3]) : "r"(a))

__device__ __forceinline__ void mma_f16(float* c, const uint32_t* a, uint32_t b0, uint32_t b1) {
    asm volatile("mma.sync.aligned.m16n8k16.row.col.f32.f16.f16.f32 "
        "{%0,%1,%2,%3}, {%4,%5,%6,%7}, {%8,%9}, {%0,%1,%2,%3};"
        : "+f"(c[0]), "+f"(c[1]), "+f"(c[2]), "+f"(c[3])
        : "r"(a[0]), "r"(a[1]), "r"(a[2]), "r"(a[3]), "r"(b0), "r"(b1));
}

// ================= scratch =================
__device__ __half g_vp16[M_ * D_];
__device__ __half g_uc16[N_ * D_];
__device__ __half g_ucT16[D_ * N_];
__device__ __half g_upT16[D_ * M_];
__device__ __half g_Sa16[M_ * N_];
__device__ __half g_SbT16[N_ * M_];
__device__ float g_Sp[4 * M_ * N_];
__device__ float g_S[M_ * N_];
__device__ float g_rp[M_], g_rc[N_];
__device__ float g_pmax[8 * N_], g_psum[8 * N_];
__device__ float g_part[M_];          // FFN term1 per row (u_p . W0)
__device__ float g_ctapart[128];      // FFN partials from dual CTAs

__device__ __forceinline__ float block_reduce_sum_256(float v, float* red) {
    int t = threadIdx.x;
    __syncthreads();
    red[t] = v;
    __syncthreads();
    #pragma unroll
    for (int s = 128; s > 0; s >>= 1) {
        if (t < s) red[t] += red[t + s];
        __syncthreads();
    }
    return red[0];
}

__device__ __forceinline__ void store_h4(__half* dst, size_t off, float4 v) {
    __half2 lo = __halves2half2(__float2half_rn(v.x), __float2half_rn(v.y));
    __half2 hi = __halves2half2(__float2half_rn(v.z), __float2half_rn(v.w));
    *(__half2*)(dst + off)     = lo;
    *(__half2*)(dst + off + 2) = hi;
}

// ================= K0: rp, rc, term1, vp16, uc16 =================
__global__ void rv_kernel(const float* __restrict__ up, const float* __restrict__ uc,
                          const float* __restrict__ wa, const float* __restrict__ W) {
    __shared__ float red[256];
    int row = blockIdx.x, t = threadIdx.x;
    if (row < M_) {
        const float* a = up + (size_t)row * D_;
        const float* w1 = wa;
        const float* w3 = wa + 2 * D_;
        const float* W0 = W + (size_t)row * 4 * D_;
        float s = 0.f, s1 = 0.f;
        for (int k = t * 4; k < D_; k += 1024) {
            float4 av = *(const float4*)(a + k);
            float4 w1v = *(const float4*)(w1 + k);
            float4 w3v = *(const float4*)(w3 + k);
            float4 W0v = *(const float4*)(W0 + k);
            s += av.x * w1v.x + av.y * w1v.y + av.z * w1v.z + av.w * w1v.w;
            s1 += av.x * W0v.x + av.y * W0v.y + av.z * W0v.z + av.w * W0v.w;
            store_h4(g_vp16, (size_t)row * D_ + k,
                     make_float4(av.x * w3v.x, av.y * w3v.y, av.z * w3v.z, av.w * w3v.w));
        }
        float tot = block_reduce_sum_256(s, red);
        if (t == 0) g_rp[row] = tot;
        float tot1 = block_reduce_sum_256(s1, red);
        if (t == 0) g_part[row] = tot1;
    } else {
        int r2 = row - M_;
        const float* a = uc + (size_t)r2 * D_;
        const float* w2 = wa + D_;
        float s = 0.f;
        for (int k = t * 4; k < D_; k += 1024) {
            float4 av = *(const float4*)(a + k);
            float4 w2v = *(const float4*)(w2 + k);
            s += av.x * w2v.x + av.y * w2v.y + av.z * w2v.z + av.w * w2v.w;
            store_h4(g_uc16, (size_t)r2 * D_ + k, av);
        }
        float tot = block_reduce_sum_256(s, red);
        if (t == 0) g_rc[r2] = tot;
    }
}

// ================= transpose both inputs (z picks src) =================
__global__ void transpose_both(const float* __restrict__ uc, const float* __restrict__ up) {
    __shared__ float t[32][33];
    int tx = threadIdx.x, ty = threadIdx.y;
    int r0 = blockIdx.y * 32, c0 = blockIdx.x * 32;
    const float* in = blockIdx.z ? up : uc;
    __half* outT = blockIdx.z ? g_upT16 : g_ucT16;
    #pragma unroll
    for (int j = 0; j < 4; j++)
        t[ty + j * 8][tx] = in[(size_t)(r0 + ty + j * 8) * D_ + c0 + tx];
    __syncthreads();
    #pragma unroll
    for (int j = 0; j < 4; j++) {
        int c = c0 + ty + j * 8;
        outT[(size_t)c * M_ + r0 + tx] = __float2half_rn(t[tx][ty + j * 8]);
    }
}

// ================= col softmax stats (partials over 128-row strips) =================
__global__ void col_stats_part(const float* __restrict__ S) {
    int tx = threadIdx.x, ty = threadIdx.y;
    int c = blockIdx.x * 128 + tx;
    int r0 = blockIdx.y * 128;
    float mx = -INFINITY, sm = 0.f;
    for (int r = ty; r < 128; r += 4) {
        float v = S[(size_t)(r0 + r) * N_ + c];
        float mn = fmaxf(mx, v);
        sm = sm * __expf(mx - mn) + __expf(v - mn);
        mx = mn;
    }
    __shared__ float m2[4][128], s2[4][128];
    m2[ty][tx] = mx; s2[ty][tx] = sm;
    __syncthreads();
    if (ty == 0) {
        float m = m2[0][tx], s = s2[0][tx];
        #pragma unroll
        for (int k = 1; k < 4; k++) {
            float mm = m2[k][tx], ss = s2[k][tx];
            float mn = fmaxf(m, mm);
            s = s * __expf(m - mn) + ss * __expf(mm - mn);
            m = mn;
        }
        g_pmax[blockIdx.y * N_ + c] = m;
        g_psum[blockIdx.y * N_ + c] = s;
    }
}

// transpose + exp, with inline 8-way partial combine (replaces col_stats_combine)
__global__ void transpose_softmax16(const float* __restrict__ S) {
    __shared__ float t[32][33];
    __shared__ float cmv[32], civ[32];
    int tx = threadIdx.x, ty = threadIdx.y;
    int r0 = blockIdx.y * 32, c0 = blockIdx.x * 32;
    if (ty == 0) {
        int c = c0 + tx;
        float m = g_pmax[c], s = g_psum[c];
        #pragma unroll
        for (int k = 1; k < 8; k++) {
            float mm = g_pmax[k * N_ + c], ss = g_psum[k * N_ + c];
            float mn = fmaxf(m, mm);
            s = s * __expf(m - mn) + ss * __expf(mm - mn);
            m = mn;
        }
        cmv[tx] = m;
        civ[tx] = 1.0f / s;
    }
    __syncthreads();
    float cm = cmv[tx], ci = civ[tx];
    #pragma unroll
    for (int j = 0; j < 4; j++) {
        float v = S[(size_t)(r0 + ty + j * 8) * N_ + c0 + tx];
        t[ty + j * 8][tx] = __expf(v - cm) * ci;
    }
    __syncthreads();
    #pragma unroll
    for (int j = 0; j < 4; j++) {
        int c = c0 + ty + j * 8;
        g_SbT16[(size_t)c * M_ + r0 + tx] = __float2half_rn(t[tx][ty + j * 8]);
    }
}

// ================= merge split-K partials + bias + row softmax =================
__global__ void merge_rowsoftmax() {
    __shared__ float red[256];
    int row = blockIdx.x, t = threadIdx.x;
    float rpv = g_rp[row];
    int j = t * 4;
    float4 a = *(const float4*)(g_Sp + (size_t)row * N_ + j);
    float4 b = *(const float4*)(g_Sp + (size_t)M_ * N_ + (size_t)row * N_ + j);
    float4 c = *(const float4*)(g_Sp + 2 * (size_t)M_ * N_ + (size_t)row * N_ + j);
    float4 d = *(const float4*)(g_Sp + 3 * (size_t)M_ * N_ + (size_t)row * N_ + j);
    float4 rc4 = *(const float4*)(g_rc + j);
    float4 o;
    o.x = a.x + b.x + c.x + d.x + rpv + rc4.x;
    o.y = a.y + b.y + c.y + d.y + rpv + rc4.y;
    o.z = a.z + b.z + c.z + d.z + rpv + rc4.z;
    o.w = a.w + b.w + c.w + d.w + rpv + rc4.w;
    *(float4*)(g_S + (size_t)row * N_ + j) = o;

    float mx = fmaxf(fmaxf(o.x, o.y), fmaxf(o.z, o.w));
    __syncthreads();
    red[t] = mx;
    __syncthreads();
    #pragma unroll
    for (int s = 128; s > 0; s >>= 1) {
        if (t < s) red[t] = fmaxf(red[t], red[t + s]);
        __syncthreads();
    }
    mx = red[0];
    float e0 = __expf(o.x - mx), e1 = __expf(o.y - mx);
    float e2 = __expf(o.z - mx), e3 = __expf(o.w - mx);
    float sum = block_reduce_sum_256(e0 + e1 + e2 + e3, red);
    float inv = 1.0f / sum;
    store_h4(g_Sa16, (size_t)row * N_ + j,
             make_float4(e0 * inv, e1 * inv, e2 * inv, e3 * inv));
}

// ================= fp16 mma GEMM core: 256x128 tile, warp tile 64x64 =================
#define NSTG 4
#define TILE_A_SZ 32768
#define TILE_B_SZ 16384
#define SMEM_GEMM (NSTG * (TILE_A_SZ + TILE_B_SZ))   // 196608

__device__ __forceinline__ void cp_tileA(uint32_t sdst, const __half* src,
                                         int row0, int ld, int k0, int tid) {
    const char* gb = (const char*)(src + (size_t)row0 * ld + k0);
    size_t rb = (size_t)ld * 2;
    #pragma unroll
    for (int it = 0; it < 8; it++) {
        int idx = tid + it * 256;
        int r = idx >> 3;
        int cb = (idx & 7) << 4;
        const void* g = gb + (size_t)r * rb + cb;
        uint32_t s = sdst + SMEM_SWIZZLE_128B(r * 128 + cb);
        asm volatile("cp.async.cg.shared.global [%0], [%1], 16;" :: "r"(s), "l"(g));
    }
}
__device__ __forceinline__ void cp_tileB(uint32_t sdst, const __half* src,
                                         int row0, int ld, int k0, int tid) {
    const char* gb = (const char*)(src + (size_t)row0 * ld + k0);
    size_t rb = (size_t)ld * 2;
    #pragma unroll
    for (int it = 0; it < 4; it++) {
        int idx = tid + it * 256;
        int r = idx >> 3;
        int cb = (idx & 7) << 4;
        const void* g = gb + (size_t)r * rb + cb;
        uint32_t s = sdst + SMEM_SWIZZLE_128B(r * 128 + cb);
        asm volatile("cp.async.cg.shared.global [%0], [%1], 16;" :: "r"(s), "l"(g));
    }
}

// warp grid 4x2 (wm=wid>>1, wn=wid&1), warp tile 64x64, acc[4(mt)][8(nt)][4]
__device__ __forceinline__ void gemm_compute(
    const __half* __restrict__ A, const __half* __restrict__ B,
    int Kdim, int c0, int ncl, int i0, int j0,
    float (&acc)[4][8][4])
{
    extern __shared__ __align__(1024) char smem[];
    uint32_t sb = smem_to_u32(smem);
    const int tid = threadIdx.x;
    const int wid = tid >> 5, lane = tid & 31;
    const int wm = wid >> 1, wn = wid & 1;

    #pragma unroll
    for (int a = 0; a < 4; a++)
        #pragma unroll
        for (int b = 0; b < 8; b++)
            #pragma unroll
            for (int c = 0; c < 4; c++) acc[a][b][c] = 0.f;

    uint32_t cA = (uint32_t)((wm * 64 + (lane & 15)) << 7) + ((lane >> 4) << 4);
    cA ^= ((cA >> 3) & 0x70);
    uint32_t rowB = (lane & 7) + ((lane >> 4) << 3);
    uint32_t cB = (uint32_t)((wn * 64 + rowB) << 7) + (((lane >> 3) & 1) << 4);
    cB ^= ((cB >> 3) & 0x70);

    #define STG_A(s) (sb + (s) * (TILE_A_SZ + TILE_B_SZ))
    #define STG_B(s) (sb + (s) * (TILE_A_SZ + TILE_B_SZ) + TILE_A_SZ)

    cp_tileA(STG_A(0), A, i0, Kdim, (c0) * 64, tid);
    cp_tileB(STG_B(0), B, j0, Kdim, (c0) * 64, tid);
    asm volatile("cp.async.commit_group;" ::: "memory");
    cp_tileA(STG_A(1), A, i0, Kdim, (c0 + 1) * 64, tid);
    cp_tileB(STG_B(1), B, j0, Kdim, (c0 + 1) * 64, tid);
    asm volatile("cp.async.commit_group;" ::: "memory");

    for (int li = 0; li < ncl; li++) {
        int s = li & 3;
        asm volatile("cp.async.wait_group 1;" ::: "memory");
        __syncthreads();
        // stage (li+2)&3 == (li-2)&3 was fully consumed before the barrier at li-1
        if (li + 2 < ncl) {
            cp_tileA(STG_A((li + 2) & 3), A, i0, Kdim, (c0 + li + 2) * 64, tid);
            cp_tileB(STG_B((li + 2) & 3), B, j0, Kdim, (c0 + li + 2) * 64, tid);
        }
        asm volatile("cp.async.commit_group;" ::: "memory");

        uint32_t aBase = STG_A(s) + cA;
        uint32_t bBase = STG_B(s) + cB;
        #pragma unroll
        for (int ks = 0; ks < 4; ks++) {
            uint32_t afr[4][4], bfr[4][4];
            #pragma unroll
            for (int mt = 0; mt < 4; mt++)
                LDSM_X4(afr[mt], (aBase + mt * 2048) ^ (ks << 5));
            #pragma unroll
            for (int p = 0; p < 4; p++)
                LDSM_X4(bfr[p], (bBase + p * 2048) ^ (ks << 5));
            #pragma unroll
            for (int mt = 0; mt < 4; mt++) {
                #pragma unroll
                for (int p = 0; p < 4; p++) {
                    mma_f16(acc[mt][p * 2 + 0], afr[mt], bfr[p][0], bfr[p][1]);
                    mma_f16(acc[mt][p * 2 + 1], afr[mt], bfr[p][2], bfr[p][3]);
                }
            }
        }
    }
    #undef STG_A
    #undef STG_B
}

// GEMM1: S partials = vp16 @ uc16^T, split-K x4
__global__ __launch_bounds__(256, 1) void gemm_splitk(
    const __half* __restrict__ A, const __half* __restrict__ B, float* __restrict__ Cp)
{
    int z = blockIdx.z;
    const int q = (D_ / 64) / 4;       // 8 chunks per split
    int i0 = blockIdx.y * 256, j0 = blockIdx.x * 128;
    float acc[4][8][4];
    gemm_compute(A, B, D_, z * q, q, i0, j0, acc);

    const int lane = threadIdx.x & 31, wid = threadIdx.x >> 5;
    const int wm = wid >> 1, wn = wid & 1;
    const int gid = lane >> 2, tig = lane & 3;
    float* C = Cp + (size_t)z * M_ * N_;
    #pragma unroll
    for (int mt = 0; mt < 4; mt++) {
        int gi = i0 + wm * 64 + mt * 16 + gid;
        #pragma unroll
        for (int nt = 0; nt < 8; nt++) {
            int gj = j0 + wn * 64 + nt * 8 + tig * 2;
            *(float2*)(C + (size_t)gi * N_ + gj) = make_float2(acc[mt][nt][0], acc[mt][nt][1]);
            *(float2*)(C + (size_t)(gi + 8) * N_ + gj) = make_float2(acc[mt][nt][2], acc[mt][nt][3]);
        }
    }
}

// GEMM2+3 fused with FFN epilogue
__global__ __launch_bounds__(256, 1) void gemm_dual_ffn(
    const __half* __restrict__ Sa, const __half* __restrict__ ucT,
    const __half* __restrict__ SbT, const __half* __restrict__ upT,
    const float* __restrict__ up, const float* __restrict__ uc,
    const float* __restrict__ W)
{
    __shared__ float red[256];
    int z = blockIdx.z;
    const __half* A = z ? SbT : Sa;
    const __half* B = z ? upT : ucT;
    int i0 = blockIdx.y * 256, j0 = blockIdx.x * 128;
    float acc[4][8][4];
    gemm_compute(A, B, N_, 0, N_ / 64, i0, j0, acc);

    const int lane = threadIdx.x & 31, wid = threadIdx.x >> 5;
    const int wm = wid >> 1, wn = wid & 1;
    const int gid = lane >> 2, tig = lane & 3;
    const float* uin = z ? uc : up;
    float part = 0.f;
    #pragma unroll
    for (int mt = 0; mt < 4; mt++) {
        int gi0 = i0 + wm * 64 + mt * 16 + gid;
        #pragma unroll
        for (int r = 0; r < 2; r++) {
            int gi = gi0 + r * 8;
            const float* Wr = W + (size_t)gi * 4 * D_;
            #pragma unroll
            for (int nt = 0; nt < 8; nt++) {
                int gj = j0 + wn * 64 + nt * 8 + tig * 2;
                float a0 = acc[mt][nt][r * 2 + 0];
                float a1 = acc[mt][nt][r * 2 + 1];
                float2 uv = *(const float2*)(uin + (size_t)gi * D_ + gj);
                if (z == 0) {
                    float2 w1 = *(const float2*)(Wr + D_ + gj);
                    float2 w2 = *(const float2*)(Wr + 2 * D_ + gj);
                    part += a0 * (w1.x + uv.x * w2.x) + a1 * (w1.y + uv.y * w2.y);
                } else {
                    float2 w3 = *(const float2*)(Wr + 3 * D_ + gj);
                    part += a0 * uv.x * w3.x + a1 * uv.y * w3.y;
                }
            }
        }
    }
    float tot = block_reduce_sum_256(part, red);
    if (threadIdx.x == 0)
        g_ctapart[z * 64 + blockIdx.y * 16 + blockIdx.x] = tot;
}

// ================= final scalar =================
__global__ void ffn_final(const float* __restrict__ b, float* __restrict__ out) {
    __shared__ float red[256];
    int t = threadIdx.x;
    float s = 0.f;
    for (int i = t; i < M_; i += 256) s += g_part[i];
    if (t < 128) s += g_ctapart[t];
    float tot = block_reduce_sum_256(s, red);
    if (t == 0) out[0] = fmaxf(tot + b[0], 0.f);
}

// ================= launch =================
extern "C" void kernel_launch(void* const* d_in, const int* in_sizes, int n_in,
                              void* d_out, int out_size) {
    const float* u_p   = (const float*)d_in[0];
    const float* u_c   = (const float*)d_in[1];
    const float* w_a   = (const float*)d_in[2];
    const float* ffn_w = (const float*)d_in[3];
    const float* ffn_b = (const float*)d_in[4];
    float* out = (float*)d_out;

    cudaFuncSetAttribute(gemm_splitk,   cudaFuncAttributeMaxDynamicSharedMemorySize, SMEM_GEMM);
    cudaFuncSetAttribute(gemm_dual_ffn, cudaFuncAttributeMaxDynamicSharedMemorySize, SMEM_GEMM);

    float *S, *Sp;
    __half *vp16, *uc16, *ucT16, *upT16, *Sa16, *SbT16;
    cudaGetSymbolAddress((void**)&S, g_S);
    cudaGetSymbolAddress((void**)&Sp, g_Sp);
    cudaGetSymbolAddress((void**)&vp16, g_vp16);
    cudaGetSymbolAddress((void**)&uc16, g_uc16);
    cudaGetSymbolAddress((void**)&ucT16, g_ucT16);
    cudaGetSymbolAddress((void**)&upT16, g_upT16);
    cudaGetSymbolAddress((void**)&Sa16, g_Sa16);
    cudaGetSymbolAddress((void**)&SbT16, g_SbT16);

    // K0: rp, rc, FFN term1, vp16, uc16
    rv_kernel<<<M_ + N_, 256>>>(u_p, u_c, w_a, ffn_w);

    // both transposed fp16 operands in one launch
    transpose_both<<<dim3(D_ / 32, M_ / 32, 2), dim3(32, 8)>>>(u_c, u_p);

    // GEMM1: S partials (split-K x4), then merge + bias + row softmax
    gemm_splitk<<<dim3(N_ / 128, M_ / 256, 4), 256, SMEM_GEMM>>>(vp16, uc16, Sp);
    merge_rowsoftmax<<<M_, 256>>>();

    // col softmax stats + transposed Sb (combine folded in)
    col_stats_part<<<dim3(N_ / 128, 8), dim3(128, 4)>>>(S);
    transpose_softmax16<<<dim3(N_ / 32, M_ / 32), dim3(32, 8)>>>(S);

    // GEMM2 + GEMM3 + FFN fused
    gemm_dual_ffn<<<dim3(D_ / 128, M_ / 256, 2), 256, SMEM_GEMM>>>(
        Sa16, ucT16, SbT16, upT16, u_p, u_c, ffn_w);

    // final scalar
    ffn_final<<<1, 256>>>(ffn_b, out);
}

// round 11
// speedup vs baseline: 2.0225x; 1.0232x over previous
#include <cuda_runtime.h>
#include <cuda_fp16.h>
#include <cstdint>
#include <math.h>

#define M_ 1024
#define N_ 1024
#define D_ 2048

// ================= helpers =================
__device__ __forceinline__ uint32_t smem_to_u32(const void* p) {
    uint32_t a;
    asm("{ .reg .u64 t; cvta.to.shared.u64 t, %1; cvt.u32.u64 %0, t; }" : "=r"(a) : "l"(p));
    return a;
}
#define SMEM_SWIZZLE_128B(b) ((b) ^ (((b) >> 3) & 0x70))

#define LDSM_X4(r, a) \
    asm volatile("ldmatrix.sync.aligned.m8n8.x4.shared.b16 {%0,%1,%2,%3}, [%4];" \
        : "=r"((r)[0]), "=r"((r)[1]), "=r"((r)[2]), "=r"((r)[3]) : "r"(a))

__device__ __forceinline__ void mma_f16(float* c, const uint32_t* a, uint32_t b0, uint32_t b1) {
    asm volatile("mma.sync.aligned.m16n8k16.row.col.f32.f16.f16.f32 "
        "{%0,%1,%2,%3}, {%4,%5,%6,%7}, {%8,%9}, {%0,%1,%2,%3};"
        : "+f"(c[0]), "+f"(c[1]), "+f"(c[2]), "+f"(c[3])
        : "r"(a[0]), "r"(a[1]), "r"(a[2]), "r"(a[3]), "r"(b0), "r"(b1));
}

// ================= scratch =================
__device__ __half g_vp16[M_ * D_];
__device__ __half g_uc16[N_ * D_];
__device__ __half g_ucT16[D_ * N_];
__device__ __half g_upT16[D_ * M_];
__device__ __half g_Sa16[M_ * N_];
__device__ __half g_SbT16[N_ * M_];
__device__ __half g_Sp16[4 * M_ * N_];   // split-K partials (fp16)
__device__ __half g_S16[M_ * N_];        // merged S (fp16, col-softmax input)
__device__ float g_rp[M_], g_rc[N_];
__device__ float g_pmax[8 * N_], g_psum[8 * N_];
__device__ float g_part[M_];             // FFN term1 per row (u_p . W0)
__device__ float g_ctapart[128];         // FFN partials from dual CTAs

__device__ __forceinline__ float block_reduce_sum_256(float v, float* red) {
    int t = threadIdx.x;
    __syncthreads();
    red[t] = v;
    __syncthreads();
    #pragma unroll
    for (int s = 128; s > 0; s >>= 1) {
        if (t < s) red[t] += red[t + s];
        __syncthreads();
    }
    return red[0];
}

__device__ __forceinline__ void store_h4(__half* dst, size_t off, float4 v) {
    __half2 lo = __halves2half2(__float2half_rn(v.x), __float2half_rn(v.y));
    __half2 hi = __halves2half2(__float2half_rn(v.z), __float2half_rn(v.w));
    *(__half2*)(dst + off)     = lo;
    *(__half2*)(dst + off + 2) = hi;
}

// ================= K0: rp, rc, term1, vp16, uc16 =================
__global__ void rv_kernel(const float* __restrict__ up, const float* __restrict__ uc,
                          const float* __restrict__ wa, const float* __restrict__ W) {
    __shared__ float red[256], red2[256];
    int row = blockIdx.x, t = threadIdx.x;
    if (row < M_) {
        const float* a = up + (size_t)row * D_;
        const float* w1 = wa;
        const float* w3 = wa + 2 * D_;
        const float* W0 = W + (size_t)row * 4 * D_;
        float s = 0.f, s1 = 0.f;
        for (int k = t * 4; k < D_; k += 1024) {
            float4 av = *(const float4*)(a + k);
            float4 w1v = *(const float4*)(w1 + k);
            float4 w3v = *(const float4*)(w3 + k);
            float4 W0v = *(const float4*)(W0 + k);
            s += av.x * w1v.x + av.y * w1v.y + av.z * w1v.z + av.w * w1v.w;
            s1 += av.x * W0v.x + av.y * W0v.y + av.z * W0v.z + av.w * W0v.w;
            store_h4(g_vp16, (size_t)row * D_ + k,
                     make_float4(av.x * w3v.x, av.y * w3v.y, av.z * w3v.z, av.w * w3v.w));
        }
        // fused dual reduction
        red[t] = s; red2[t] = s1;
        __syncthreads();
        #pragma unroll
        for (int st = 128; st > 0; st >>= 1) {
            if (t < st) { red[t] += red[t + st]; red2[t] += red2[t + st]; }
            __syncthreads();
        }
        if (t == 0) { g_rp[row] = red[0]; g_part[row] = red2[0]; }
    } else {
        int r2 = row - M_;
        const float* a = uc + (size_t)r2 * D_;
        const float* w2 = wa + D_;
        float s = 0.f;
        for (int k = t * 4; k < D_; k += 1024) {
            float4 av = *(const float4*)(a + k);
            float4 w2v = *(const float4*)(w2 + k);
            s += av.x * w2v.x + av.y * w2v.y + av.z * w2v.z + av.w * w2v.w;
            store_h4(g_uc16, (size_t)r2 * D_ + k, av);
        }
        float tot = block_reduce_sum_256(s, red);
        if (t == 0) g_rc[r2] = tot;
    }
}

// ================= transpose both inputs (z picks src) =================
__global__ void transpose_both(const float* __restrict__ uc, const float* __restrict__ up) {
    __shared__ float t[32][33];
    int tx = threadIdx.x, ty = threadIdx.y;
    int r0 = blockIdx.y * 32, c0 = blockIdx.x * 32;
    const float* in = blockIdx.z ? up : uc;
    __half* outT = blockIdx.z ? g_upT16 : g_ucT16;
    #pragma unroll
    for (int j = 0; j < 4; j++)
        t[ty + j * 8][tx] = in[(size_t)(r0 + ty + j * 8) * D_ + c0 + tx];
    __syncthreads();
    #pragma unroll
    for (int j = 0; j < 4; j++) {
        int c = c0 + ty + j * 8;
        outT[(size_t)c * M_ + r0 + tx] = __float2half_rn(t[tx][ty + j * 8]);
    }
}

// ================= col softmax stats over fp16 S =================
__global__ void col_stats_part() {
    int tx = threadIdx.x, ty = threadIdx.y;
    int c = blockIdx.x * 128 + tx;
    int r0 = blockIdx.y * 128;
    float mx = -INFINITY, sm = 0.f;
    for (int r = ty; r < 128; r += 4) {
        float v = __half2float(g_S16[(size_t)(r0 + r) * N_ + c]);
        float mn = fmaxf(mx, v);
        sm = sm * __expf(mx - mn) + __expf(v - mn);
        mx = mn;
    }
    __shared__ float m2[4][128], s2[4][128];
    m2[ty][tx] = mx; s2[ty][tx] = sm;
    __syncthreads();
    if (ty == 0) {
        float m = m2[0][tx], s = s2[0][tx];
        #pragma unroll
        for (int k = 1; k < 4; k++) {
            float mm = m2[k][tx], ss = s2[k][tx];
            float mn = fmaxf(m, mm);
            s = s * __expf(m - mn) + ss * __expf(mm - mn);
            m = mn;
        }
        g_pmax[blockIdx.y * N_ + c] = m;
        g_psum[blockIdx.y * N_ + c] = s;
    }
}

// transpose + exp from fp16 S, with inline 8-way partial combine
__global__ void transpose_softmax16() {
    __shared__ float t[32][33];
    __shared__ float cmv[32], civ[32];
    int tx = threadIdx.x, ty = threadIdx.y;
    int r0 = blockIdx.y * 32, c0 = blockIdx.x * 32;
    if (ty == 0) {
        int c = c0 + tx;
        float m = g_pmax[c], s = g_psum[c];
        #pragma unroll
        for (int k = 1; k < 8; k++) {
            float mm = g_pmax[k * N_ + c], ss = g_psum[k * N_ + c];
            float mn = fmaxf(m, mm);
            s = s * __expf(m - mn) + ss * __expf(mm - mn);
            m = mn;
        }
        cmv[tx] = m;
        civ[tx] = 1.0f / s;
    }
    __syncthreads();
    float cm = cmv[tx], ci = civ[tx];
    #pragma unroll
    for (int j = 0; j < 4; j++) {
        float v = __half2float(g_S16[(size_t)(r0 + ty + j * 8) * N_ + c0 + tx]);
        t[ty + j * 8][tx] = __expf(v - cm) * ci;
    }
    __syncthreads();
    #pragma unroll
    for (int j = 0; j < 4; j++) {
        int c = c0 + ty + j * 8;
        g_SbT16[(size_t)c * M_ + r0 + tx] = __float2half_rn(t[tx][ty + j * 8]);
    }
}

// ================= merge fp16 split-K partials + bias + row softmax =================
__global__ void merge_rowsoftmax() {
    __shared__ float red[256];
    int row = blockIdx.x, t = threadIdx.x;
    float rpv = g_rp[row];
    int j = t * 4;
    float4 rc4 = *(const float4*)(g_rc + j);
    float4 o = make_float4(rpv + rc4.x, rpv + rc4.y, rpv + rc4.z, rpv + rc4.w);
    #pragma unroll
    for (int z = 0; z < 4; z++) {
        const __half* P = g_Sp16 + (size_t)z * M_ * N_ + (size_t)row * N_ + j;
        __half2 p01 = *(const __half2*)(P);
        __half2 p23 = *(const __half2*)(P + 2);
        float2 f01 = __half22float2(p01);
        float2 f23 = __half22float2(p23);
        o.x += f01.x; o.y += f01.y; o.z += f23.x; o.w += f23.y;
    }
    // store merged S as fp16 for the column pass
    store_h4(g_S16, (size_t)row * N_ + j, o);

    float mx = fmaxf(fmaxf(o.x, o.y), fmaxf(o.z, o.w));
    __syncthreads();
    red[t] = mx;
    __syncthreads();
    #pragma unroll
    for (int s = 128; s > 0; s >>= 1) {
        if (t < s) red[t] = fmaxf(red[t], red[t + s]);
        __syncthreads();
    }
    mx = red[0];
    float e0 = __expf(o.x - mx), e1 = __expf(o.y - mx);
    float e2 = __expf(o.z - mx), e3 = __expf(o.w - mx);
    float sum = block_reduce_sum_256(e0 + e1 + e2 + e3, red);
    float inv = 1.0f / sum;
    store_h4(g_Sa16, (size_t)row * N_ + j,
             make_float4(e0 * inv, e1 * inv, e2 * inv, e3 * inv));
}

// ================= fp16 mma GEMM core: 256x128 tile, warp tile 64x64 =================
#define NSTG 4
#define TILE_A_SZ 32768
#define TILE_B_SZ 16384
#define SMEM_GEMM (NSTG * (TILE_A_SZ + TILE_B_SZ))   // 196608

__device__ __forceinline__ void cp_tileA(uint32_t sdst, const __half* src,
                                         int row0, int ld, int k0, int tid) {
    const char* gb = (const char*)(src + (size_t)row0 * ld + k0);
    size_t rb = (size_t)ld * 2;
    #pragma unroll
    for (int it = 0; it < 8; it++) {
        int idx = tid + it * 256;
        int r = idx >> 3;
        int cb = (idx & 7) << 4;
        const void* g = gb + (size_t)r * rb + cb;
        uint32_t s = sdst + SMEM_SWIZZLE_128B(r * 128 + cb);
        asm volatile("cp.async.cg.shared.global [%0], [%1], 16;" :: "r"(s), "l"(g));
    }
}
__device__ __forceinline__ void cp_tileB(uint32_t sdst, const __half* src,
                                         int row0, int ld, int k0, int tid) {
    const char* gb = (const char*)(src + (size_t)row0 * ld + k0);
    size_t rb = (size_t)ld * 2;
    #pragma unroll
    for (int it = 0; it < 4; it++) {
        int idx = tid + it * 256;
        int r = idx >> 3;
        int cb = (idx & 7) << 4;
        const void* g = gb + (size_t)r * rb + cb;
        uint32_t s = sdst + SMEM_SWIZZLE_128B(r * 128 + cb);
        asm volatile("cp.async.cg.shared.global [%0], [%1], 16;" :: "r"(s), "l"(g));
    }
}

// warp grid 4x2 (wm=wid>>1, wn=wid&1), warp tile 64x64, acc[4(mt)][8(nt)][4]
__device__ __forceinline__ void gemm_compute(
    const __half* __restrict__ A, const __half* __restrict__ B,
    int Kdim, int c0, int ncl, int i0, int j0,
    float (&acc)[4][8][4])
{
    extern __shared__ __align__(1024) char smem[];
    uint32_t sb = smem_to_u32(smem);
    const int tid = threadIdx.x;
    const int wid = tid >> 5, lane = tid & 31;
    const int wm = wid >> 1, wn = wid & 1;

    #pragma unroll
    for (int a = 0; a < 4; a++)
        #pragma unroll
        for (int b = 0; b < 8; b++)
            #pragma unroll
            for (int c = 0; c < 4; c++) acc[a][b][c] = 0.f;

    uint32_t cA = (uint32_t)((wm * 64 + (lane & 15)) << 7) + ((lane >> 4) << 4);
    cA ^= ((cA >> 3) & 0x70);
    uint32_t rowB = (lane & 7) + ((lane >> 4) << 3);
    uint32_t cB = (uint32_t)((wn * 64 + rowB) << 7) + (((lane >> 3) & 1) << 4);
    cB ^= ((cB >> 3) & 0x70);

    #define STG_A(s) (sb + (s) * (TILE_A_SZ + TILE_B_SZ))
    #define STG_B(s) (sb + (s) * (TILE_A_SZ + TILE_B_SZ) + TILE_A_SZ)

    cp_tileA(STG_A(0), A, i0, Kdim, (c0) * 64, tid);
    cp_tileB(STG_B(0), B, j0, Kdim, (c0) * 64, tid);
    asm volatile("cp.async.commit_group;" ::: "memory");
    cp_tileA(STG_A(1), A, i0, Kdim, (c0 + 1) * 64, tid);
    cp_tileB(STG_B(1), B, j0, Kdim, (c0 + 1) * 64, tid);
    asm volatile("cp.async.commit_group;" ::: "memory");

    for (int li = 0; li < ncl; li++) {
        int s = li & 3;
        asm volatile("cp.async.wait_group 1;" ::: "memory");
        __syncthreads();
        if (li + 2 < ncl) {
            cp_tileA(STG_A((li + 2) & 3), A, i0, Kdim, (c0 + li + 2) * 64, tid);
            cp_tileB(STG_B((li + 2) & 3), B, j0, Kdim, (c0 + li + 2) * 64, tid);
        }
        asm volatile("cp.async.commit_group;" ::: "memory");

        uint32_t aBase = STG_A(s) + cA;
        uint32_t bBase = STG_B(s) + cB;
        #pragma unroll
        for (int ks = 0; ks < 4; ks++) {
            uint32_t afr[4][4], bfr[4][4];
            #pragma unroll
            for (int mt = 0; mt < 4; mt++)
                LDSM_X4(afr[mt], (aBase + mt * 2048) ^ (ks << 5));
            #pragma unroll
            for (int p = 0; p < 4; p++)
                LDSM_X4(bfr[p], (bBase + p * 2048) ^ (ks << 5));
            #pragma unroll
            for (int mt = 0; mt < 4; mt++) {
                #pragma unroll
                for (int p = 0; p < 4; p++) {
                    mma_f16(acc[mt][p * 2 + 0], afr[mt], bfr[p][0], bfr[p][1]);
                    mma_f16(acc[mt][p * 2 + 1], afr[mt], bfr[p][2], bfr[p][3]);
                }
            }
        }
    }
    #undef STG_A
    #undef STG_B
}

// GEMM1: S partials = vp16 @ uc16^T, split-K x4, fp16 partial output
__global__ __launch_bounds__(256, 1) void gemm_splitk(
    const __half* __restrict__ A, const __half* __restrict__ B, __half* __restrict__ Cp)
{
    int z = blockIdx.z;
    const int q = (D_ / 64) / 4;       // 8 chunks per split
    int i0 = blockIdx.y * 256, j0 = blockIdx.x * 128;
    float acc[4][8][4];
    gemm_compute(A, B, D_, z * q, q, i0, j0, acc);

    const int lane = threadIdx.x & 31, wid = threadIdx.x >> 5;
    const int wm = wid >> 1, wn = wid & 1;
    const int gid = lane >> 2, tig = lane & 3;
    __half* C = Cp + (size_t)z * M_ * N_;
    #pragma unroll
    for (int mt = 0; mt < 4; mt++) {
        int gi = i0 + wm * 64 + mt * 16 + gid;
        #pragma unroll
        for (int nt = 0; nt < 8; nt++) {
            int gj = j0 + wn * 64 + nt * 8 + tig * 2;
            *(__half2*)(C + (size_t)gi * N_ + gj) =
                __floats2half2_rn(acc[mt][nt][0], acc[mt][nt][1]);
            *(__half2*)(C + (size_t)(gi + 8) * N_ + gj) =
                __floats2half2_rn(acc[mt][nt][2], acc[mt][nt][3]);
        }
    }
}

// GEMM2+3 fused with FFN epilogue
__global__ __launch_bounds__(256, 1) void gemm_dual_ffn(
    const __half* __restrict__ Sa, const __half* __restrict__ ucT,
    const __half* __restrict__ SbT, const __half* __restrict__ upT,
    const float* __restrict__ up, const float* __restrict__ uc,
    const float* __restrict__ W)
{
    __shared__ float red[256];
    int z = blockIdx.z;
    const __half* A = z ? SbT : Sa;
    const __half* B = z ? upT : ucT;
    int i0 = blockIdx.y * 256, j0 = blockIdx.x * 128;
    float acc[4][8][4];
    gemm_compute(A, B, N_, 0, N_ / 64, i0, j0, acc);

    const int lane = threadIdx.x & 31, wid = threadIdx.x >> 5;
    const int wm = wid >> 1, wn = wid & 1;
    const int gid = lane >> 2, tig = lane & 3;
    const float* uin = z ? uc : up;
    float part = 0.f;
    #pragma unroll
    for (int mt = 0; mt < 4; mt++) {
        int gi0 = i0 + wm * 64 + mt * 16 + gid;
        #pragma unroll
        for (int r = 0; r < 2; r++) {
            int gi = gi0 + r * 8;
            const float* Wr = W + (size_t)gi * 4 * D_;
            #pragma unroll
            for (int nt = 0; nt < 8; nt++) {
                int gj = j0 + wn * 64 + nt * 8 + tig * 2;
                float a0 = acc[mt][nt][r * 2 + 0];
                float a1 = acc[mt][nt][r * 2 + 1];
                float2 uv = *(const float2*)(uin + (size_t)gi * D_ + gj);
                if (z == 0) {
                    float2 w1 = *(const float2*)(Wr + D_ + gj);
                    float2 w2 = *(const float2*)(Wr + 2 * D_ + gj);
                    part += a0 * (w1.x + uv.x * w2.x) + a1 * (w1.y + uv.y * w2.y);
                } else {
                    float2 w3 = *(const float2*)(Wr + 3 * D_ + gj);
                    part += a0 * uv.x * w3.x + a1 * uv.y * w3.y;
                }
            }
        }
    }
    float tot = block_reduce_sum_256(part, red);
    if (threadIdx.x == 0)
        g_ctapart[z * 64 + blockIdx.y * 16 + blockIdx.x] = tot;
}

// ================= final scalar =================
__global__ void ffn_final(const float* __restrict__ b, float* __restrict__ out) {
    __shared__ float red[256];
    int t = threadIdx.x;
    float s = 0.f;
    for (int i = t; i < M_; i += 256) s += g_part[i];
    if (t < 128) s += g_ctapart[t];
    float tot = block_reduce_sum_256(s, red);
    if (t == 0) out[0] = fmaxf(tot + b[0], 0.f);
}

// ================= launch =================
extern "C" void kernel_launch(void* const* d_in, const int* in_sizes, int n_in,
                              void* d_out, int out_size) {
    const float* u_p   = (const float*)d_in[0];
    const float* u_c   = (const float*)d_in[1];
    const float* w_a   = (const float*)d_in[2];
    const float* ffn_w = (const float*)d_in[3];
    const float* ffn_b = (const float*)d_in[4];
    float* out = (float*)d_out;

    cudaFuncSetAttribute(gemm_splitk,   cudaFuncAttributeMaxDynamicSharedMemorySize, SMEM_GEMM);
    cudaFuncSetAttribute(gemm_dual_ffn, cudaFuncAttributeMaxDynamicSharedMemorySize, SMEM_GEMM);

    __half *vp16, *uc16, *ucT16, *upT16, *Sa16, *SbT16, *Sp16;
    cudaGetSymbolAddress((void**)&vp16, g_vp16);
    cudaGetSymbolAddress((void**)&uc16, g_uc16);
    cudaGetSymbolAddress((void**)&ucT16, g_ucT16);
    cudaGetSymbolAddress((void**)&upT16, g_upT16);
    cudaGetSymbolAddress((void**)&Sa16, g_Sa16);
    cudaGetSymbolAddress((void**)&SbT16, g_SbT16);
    cudaGetSymbolAddress((void**)&Sp16, g_Sp16);

    // K0: rp, rc, FFN term1, vp16, uc16
    rv_kernel<<<M_ + N_, 256>>>(u_p, u_c, w_a, ffn_w);

    // both transposed fp16 operands in one launch
    transpose_both<<<dim3(D_ / 32, M_ / 32, 2), dim3(32, 8)>>>(u_c, u_p);

    // GEMM1: fp16 S partials (split-K x4), then merge + bias + row softmax
    gemm_splitk<<<dim3(N_ / 128, M_ / 256, 4), 256, SMEM_GEMM>>>(vp16, uc16, Sp16);
    merge_rowsoftmax<<<M_, 256>>>();

    // col softmax stats + transposed Sb (fp16 S input)
    col_stats_part<<<dim3(N_ / 128, 8), dim3(128, 4)>>>();
    transpose_softmax16<<<dim3(N_ / 32, M_ / 32), dim3(32, 8)>>>();

    // GEMM2 + GEMM3 + FFN fused
    gemm_dual_ffn<<<dim3(D_ / 128, M_ / 256, 2), 256, SMEM_GEMM>>>(
        Sa16, ucT16, SbT16, upT16, u_p, u_c, ffn_w);

    // final scalar
    ffn_final<<<1, 256>>>(ffn_b, out);
}

// round 12
// speedup vs baseline: 2.2317x; 1.1034x over previous
#include <cuda_runtime.h>
#include <cuda_fp16.h>
#include <cstdint>
#include <math.h>

#define M_ 1024
#define N_ 1024
#define D_ 2048

// ================= helpers =================
__device__ __forceinline__ uint32_t smem_to_u32(const void* p) {
    uint32_t a;
    asm("{ .reg .u64 t; cvta.to.shared.u64 t, %1; cvt.u32.u64 %0, t; }" : "=r"(a) : "l"(p));
    return a;
}
#define SMEM_SWIZZLE_128B(b) ((b) ^ (((b) >> 3) & 0x70))

#define LDSM_X4(r, a) \
    asm volatile("ldmatrix.sync.aligned.m8n8.x4.shared.b16 {%0,%1,%2,%3}, [%4];" \
        : "=r"((r)[0]), "=r"((r)[1]), "=r"((r)[2]), "=r"((r)[3]) : "r"(a))
#define LDSM_X4_T(r, a) \
    asm volatile("ldmatrix.sync.aligned.m8n8.x4.trans.shared.b16 {%0,%1,%2,%3}, [%4];" \
        : "=r"((r)[0]), "=r"((r)[1]), "=r"((r)[2]), "=r"((r)[3]) : "r"(a))

__device__ __forceinline__ void mma_f16(float* c, const uint32_t* a, uint32_t b0, uint32_t b1) {
    asm volatile("mma.sync.aligned.m16n8k16.row.col.f32.f16.f16.f32 "
        "{%0,%1,%2,%3}, {%4,%5,%6,%7}, {%8,%9}, {%0,%1,%2,%3};"
        : "+f"(c[0]), "+f"(c[1]), "+f"(c[2]), "+f"(c[3])
        : "r"(a[0]), "r"(a[1]), "r"(a[2]), "r"(a[3]), "r"(b0), "r"(b1));
}

__device__ __forceinline__ float warp_sum(float v) {
    #pragma unroll
    for (int o = 16; o > 0; o >>= 1) v += __shfl_xor_sync(0xffffffffu, v, o);
    return v;
}
__device__ __forceinline__ float warp_max(float v) {
    #pragma unroll
    for (int o = 16; o > 0; o >>= 1) v = fmaxf(v, __shfl_xor_sync(0xffffffffu, v, o));
    return v;
}

// ================= scratch =================
__device__ __half g_vp16[M_ * D_];
__device__ __half g_up16[M_ * D_];
__device__ __half g_uc16[N_ * D_];
__device__ __half g_Sa16[M_ * N_];
__device__ __half g_SbT16[N_ * M_];
__device__ __half g_Sp16[4 * M_ * N_];   // split-K partials (fp16)
__device__ __half g_S16[M_ * N_];        // merged S (fp16)
__device__ float g_rp[M_], g_rc[N_];
__device__ float g_pmax[8 * N_], g_psum[8 * N_];
__device__ float g_part[M_];             // FFN term1 per row (u_p . W0)
__device__ float g_ctapart[128];         // FFN partials from dual CTAs

__device__ __forceinline__ void store_h4(__half* dst, size_t off, float4 v) {
    __half2 lo = __halves2half2(__float2half_rn(v.x), __float2half_rn(v.y));
    __half2 hi = __halves2half2(__float2half_rn(v.z), __float2half_rn(v.w));
    *(__half2*)(dst + off)     = lo;
    *(__half2*)(dst + off + 2) = hi;
}

// ================= K0: rp, rc, term1, vp16, up16, uc16 =================
__global__ void rv_kernel(const float* __restrict__ up, const float* __restrict__ uc,
                          const float* __restrict__ wa, const float* __restrict__ W) {
    __shared__ float sm1[8], sm2[8];
    int row = blockIdx.x, t = threadIdx.x;
    int w = t >> 5, l = t & 31;
    if (row < M_) {
        const float* a = up + (size_t)row * D_;
        const float* w1 = wa;
        const float* w3 = wa + 2 * D_;
        const float* W0 = W + (size_t)row * 4 * D_;
        float s = 0.f, s1 = 0.f;
        for (int k = t * 4; k < D_; k += 1024) {
            float4 av = *(const float4*)(a + k);
            float4 w1v = *(const float4*)(w1 + k);
            float4 w3v = *(const float4*)(w3 + k);
            float4 W0v = *(const float4*)(W0 + k);
            s += av.x * w1v.x + av.y * w1v.y + av.z * w1v.z + av.w * w1v.w;
            s1 += av.x * W0v.x + av.y * W0v.y + av.z * W0v.z + av.w * W0v.w;
            store_h4(g_vp16, (size_t)row * D_ + k,
                     make_float4(av.x * w3v.x, av.y * w3v.y, av.z * w3v.z, av.w * w3v.w));
            store_h4(g_up16, (size_t)row * D_ + k, av);
        }
        s = warp_sum(s); s1 = warp_sum(s1);
        if (l == 0) { sm1[w] = s; sm2[w] = s1; }
        __syncthreads();
        if (t == 0) {
            float a0 = 0.f, b0 = 0.f;
            #pragma unroll
            for (int i = 0; i < 8; i++) { a0 += sm1[i]; b0 += sm2[i]; }
            g_rp[row] = a0; g_part[row] = b0;
        }
    } else {
        int r2 = row - M_;
        const float* a = uc + (size_t)r2 * D_;
        const float* w2 = wa + D_;
        float s = 0.f;
        for (int k = t * 4; k < D_; k += 1024) {
            float4 av = *(const float4*)(a + k);
            float4 w2v = *(const float4*)(w2 + k);
            s += av.x * w2v.x + av.y * w2v.y + av.z * w2v.z + av.w * w2v.w;
            store_h4(g_uc16, (size_t)r2 * D_ + k, av);
        }
        s = warp_sum(s);
        if (l == 0) sm1[w] = s;
        __syncthreads();
        if (t == 0) {
            float a0 = 0.f;
            #pragma unroll
            for (int i = 0; i < 8; i++) a0 += sm1[i];
            g_rc[r2] = a0;
        }
    }
}

// ================= col softmax stats over fp16 S =================
__global__ void col_stats_part() {
    int tx = threadIdx.x, ty = threadIdx.y;
    int c = blockIdx.x * 128 + tx;
    int r0 = blockIdx.y * 128;
    float mx = -INFINITY, sm = 0.f;
    for (int r = ty; r < 128; r += 4) {
        float v = __half2float(g_S16[(size_t)(r0 + r) * N_ + c]);
        float mn = fmaxf(mx, v);
        sm = sm * __expf(mx - mn) + __expf(v - mn);
        mx = mn;
    }
    __shared__ float m2[4][128], s2[4][128];
    m2[ty][tx] = mx; s2[ty][tx] = sm;
    __syncthreads();
    if (ty == 0) {
        float m = m2[0][tx], s = s2[0][tx];
        #pragma unroll
        for (int k = 1; k < 4; k++) {
            float mm = m2[k][tx], ss = s2[k][tx];
            float mn = fmaxf(m, mm);
            s = s * __expf(m - mn) + ss * __expf(mm - mn);
            m = mn;
        }
        g_pmax[blockIdx.y * N_ + c] = m;
        g_psum[blockIdx.y * N_ + c] = s;
    }
}

// transpose + exp from fp16 S, with inline 8-way partial combine
__global__ void transpose_softmax16() {
    __shared__ float t[32][33];
    __shared__ float cmv[32], civ[32];
    int tx = threadIdx.x, ty = threadIdx.y;
    int r0 = blockIdx.y * 32, c0 = blockIdx.x * 32;
    if (ty == 0) {
        int c = c0 + tx;
        float m = g_pmax[c], s = g_psum[c];
        #pragma unroll
        for (int k = 1; k < 8; k++) {
            float mm = g_pmax[k * N_ + c], ss = g_psum[k * N_ + c];
            float mn = fmaxf(m, mm);
            s = s * __expf(m - mn) + ss * __expf(mm - mn);
            m = mn;
        }
        cmv[tx] = m;
        civ[tx] = 1.0f / s;
    }
    __syncthreads();
    float cm = cmv[tx], ci = civ[tx];
    #pragma unroll
    for (int j = 0; j < 4; j++) {
        float v = __half2float(g_S16[(size_t)(r0 + ty + j * 8) * N_ + c0 + tx]);
        t[ty + j * 8][tx] = __expf(v - cm) * ci;
    }
    __syncthreads();
    #pragma unroll
    for (int j = 0; j < 4; j++) {
        int c = c0 + ty + j * 8;
        g_SbT16[(size_t)c * M_ + r0 + tx] = __float2half_rn(t[tx][ty + j * 8]);
    }
}

// ================= merge fp16 split-K partials + bias + row softmax =================
__global__ void merge_rowsoftmax() {
    __shared__ float smx[8], ssm[8];
    int row = blockIdx.x, t = threadIdx.x;
    int w = t >> 5, l = t & 31;
    float rpv = g_rp[row];
    int j = t * 4;
    float4 rc4 = *(const float4*)(g_rc + j);
    float4 o = make_float4(rpv + rc4.x, rpv + rc4.y, rpv + rc4.z, rpv + rc4.w);
    #pragma unroll
    for (int z = 0; z < 4; z++) {
        const __half* P = g_Sp16 + (size_t)z * M_ * N_ + (size_t)row * N_ + j;
        float2 f01 = __half22float2(*(const __half2*)(P));
        float2 f23 = __half22float2(*(const __half2*)(P + 2));
        o.x += f01.x; o.y += f01.y; o.z += f23.x; o.w += f23.y;
    }
    store_h4(g_S16, (size_t)row * N_ + j, o);

    float mx = warp_max(fmaxf(fmaxf(o.x, o.y), fmaxf(o.z, o.w)));
    if (l == 0) smx[w] = mx;
    __syncthreads();
    mx = smx[0];
    #pragma unroll
    for (int i = 1; i < 8; i++) mx = fmaxf(mx, smx[i]);

    float e0 = __expf(o.x - mx), e1 = __expf(o.y - mx);
    float e2 = __expf(o.z - mx), e3 = __expf(o.w - mx);
    float s = warp_sum(e0 + e1 + e2 + e3);
    if (l == 0) ssm[w] = s;
    __syncthreads();
    s = ssm[0];
    #pragma unroll
    for (int i = 1; i < 8; i++) s += ssm[i];
    float inv = 1.0f / s;
    store_h4(g_Sa16, (size_t)row * N_ + j,
             make_float4(e0 * inv, e1 * inv, e2 * inv, e3 * inv));
}

// ================= fp16 mma GEMM core: 256x128 tile, warp tile 64x64 =================
#define NSTG 4
#define TILE_A_SZ 32768
#define TILE_B_SZ 16384
#define SMEM_GEMM (NSTG * (TILE_A_SZ + TILE_B_SZ))   // 196608

__device__ __forceinline__ void cp_tileA(uint32_t sdst, const __half* src,
                                         int row0, int ld, int k0, int tid) {
    const char* gb = (const char*)(src + (size_t)row0 * ld + k0);
    size_t rb = (size_t)ld * 2;
    #pragma unroll
    for (int it = 0; it < 8; it++) {
        int idx = tid + it * 256;
        int r = idx >> 3;
        int cb = (idx & 7) << 4;
        const void* g = gb + (size_t)r * rb + cb;
        uint32_t s = sdst + SMEM_SWIZZLE_128B(r * 128 + cb);
        asm volatile("cp.async.cg.shared.global [%0], [%1], 16;" :: "r"(s), "l"(g));
    }
}
// non-trans B: 128 rows (n) x 64 k fp16, rows k-contiguous
__device__ __forceinline__ void cp_tileB(uint32_t sdst, const __half* src,
                                         int row0, int ld, int k0, int tid) {
    const char* gb = (const char*)(src + (size_t)row0 * ld + k0);
    size_t rb = (size_t)ld * 2;
    #pragma unroll
    for (int it = 0; it < 4; it++) {
        int idx = tid + it * 256;
        int r = idx >> 3;
        int cb = (idx & 7) << 4;
        const void* g = gb + (size_t)r * rb + cb;
        uint32_t s = sdst + SMEM_SWIZZLE_128B(r * 128 + cb);
        asm volatile("cp.async.cg.shared.global [%0], [%1], 16;" :: "r"(s), "l"(g));
    }
}
// trans B: 64 k-rows x 128 j-cols fp16 (256B gmem rows) -> two 64x128B swizzled segments
__device__ __forceinline__ void cp_tileB_trans(uint32_t sdst, const __half* src,
                                               int krow0, int ld, int j0, int tid) {
    const char* gb = (const char*)(src + (size_t)krow0 * ld + j0);
    size_t rb = (size_t)ld * 2;
    #pragma unroll
    for (int it = 0; it < 4; it++) {
        int idx = tid + it * 256;
        int r = idx >> 4;             // 0..63 k-row
        int c16 = idx & 15;           // 16B chunk (8 cols)
        const void* g = gb + (size_t)r * rb + c16 * 16;
        uint32_t off = ((uint32_t)(c16 >> 3) << 13) + ((uint32_t)r << 7) + ((c16 & 7) << 4);
        uint32_t s = sdst + SMEM_SWIZZLE_128B(off);
        asm volatile("cp.async.cg.shared.global [%0], [%1], 16;" :: "r"(s), "l"(g));
    }
}

// warp grid 4x2 (wm=wid>>1, wn=wid&1), warp tile 64x64, acc[4(mt)][8(nt)][4]
// TB=false: B rows are output-cols (k-contig). TB=true: B rows are k (j-contig), via ldmatrix.trans.
template<bool TB>
__device__ __forceinline__ void gemm_compute(
    const __half* __restrict__ A, const __half* __restrict__ B, int ldB,
    int Kdim, int c0, int ncl, int i0, int j0,
    float (&acc)[4][8][4])
{
    extern __shared__ __align__(1024) char smem[];
    uint32_t sb = smem_to_u32(smem);
    const int tid = threadIdx.x;
    const int wid = tid >> 5, lane = tid & 31;
    const int wm = wid >> 1, wn = wid & 1;

    #pragma unroll
    for (int a = 0; a < 4; a++)
        #pragma unroll
        for (int b = 0; b < 8; b++)
            #pragma unroll
            for (int c = 0; c < 4; c++) acc[a][b][c] = 0.f;

    uint32_t cA = (uint32_t)((wm * 64 + (lane & 15)) << 7) + ((lane >> 4) << 4);
    cA ^= ((cA >> 3) & 0x70);
    uint32_t cB;
    if (TB) {
        // tile0: k 0-7 / tile1: k 8-15 (lane>>3 &1), j-half (lane>>4)*8
        uint32_t kr = (lane & 7) + (((lane >> 3) & 1) << 3);
        uint32_t jc = ((lane >> 4) & 1) << 3;
        cB = ((uint32_t)wn << 13) + (kr << 7) + (jc << 1);
        cB ^= ((cB >> 3) & 0x70);
    } else {
        uint32_t rowB = (lane & 7) + ((lane >> 4) << 3);
        cB = (uint32_t)((wn * 64 + rowB) << 7) + (((lane >> 3) & 1) << 4);
        cB ^= ((cB >> 3) & 0x70);
    }

    #define STG_A(s) (sb + (s) * (TILE_A_SZ + TILE_B_SZ))
    #define STG_B(s) (sb + (s) * (TILE_A_SZ + TILE_B_SZ) + TILE_A_SZ)
    #define LOAD_CHUNK(st, ci) do { \
        cp_tileA(STG_A(st), A, i0, Kdim, (ci) * 64, tid); \
        if (TB) cp_tileB_trans(STG_B(st), B, (ci) * 64, ldB, j0, tid); \
        else    cp_tileB(STG_B(st), B, j0, ldB, (ci) * 64, tid); \
    } while (0)

    LOAD_CHUNK(0, c0);
    asm volatile("cp.async.commit_group;" ::: "memory");
    LOAD_CHUNK(1, c0 + 1);
    asm volatile("cp.async.commit_group;" ::: "memory");

    for (int li = 0; li < ncl; li++) {
        int s = li & 3;
        asm volatile("cp.async.wait_group 1;" ::: "memory");
        __syncthreads();
        if (li + 2 < ncl) LOAD_CHUNK((li + 2) & 3, c0 + li + 2);
        asm volatile("cp.async.commit_group;" ::: "memory");

        uint32_t aBase = STG_A(s) + cA;
        uint32_t bBase = STG_B(s) + cB;
        #pragma unroll
        for (int ks = 0; ks < 4; ks++) {
            uint32_t afr[4][4], bfr[4][4];
            #pragma unroll
            for (int mt = 0; mt < 4; mt++)
                LDSM_X4(afr[mt], (aBase + mt * 2048) ^ (ks << 5));
            #pragma unroll
            for (int p = 0; p < 4; p++) {
                if (TB) LDSM_X4_T(bfr[p], (bBase + ks * 2048) ^ (p << 5));
                else    LDSM_X4(bfr[p], (bBase + p * 2048) ^ (ks << 5));
            }
            #pragma unroll
            for (int mt = 0; mt < 4; mt++) {
                #pragma unroll
                for (int p = 0; p < 4; p++) {
                    mma_f16(acc[mt][p * 2 + 0], afr[mt], bfr[p][0], bfr[p][1]);
                    mma_f16(acc[mt][p * 2 + 1], afr[mt], bfr[p][2], bfr[p][3]);
                }
            }
        }
    }
    #undef STG_A
    #undef STG_B
    #undef LOAD_CHUNK
}

// GEMM1: S partials = vp16 @ uc16^T, split-K x4, fp16 partial output
__global__ __launch_bounds__(256, 1) void gemm_splitk(
    const __half* __restrict__ A, const __half* __restrict__ B, __half* __restrict__ Cp)
{
    int z = blockIdx.z;
    const int q = (D_ / 64) / 4;       // 8 chunks per split
    int i0 = blockIdx.y * 256, j0 = blockIdx.x * 128;
    float acc[4][8][4];
    gemm_compute<false>(A, B, D_, D_, z * q, q, i0, j0, acc);

    const int lane = threadIdx.x & 31, wid = threadIdx.x >> 5;
    const int wm = wid >> 1, wn = wid & 1;
    const int gid = lane >> 2, tig = lane & 3;
    __half* C = Cp + (size_t)z * M_ * N_;
    #pragma unroll
    for (int mt = 0; mt < 4; mt++) {
        int gi = i0 + wm * 64 + mt * 16 + gid;
        #pragma unroll
        for (int nt = 0; nt < 8; nt++) {
            int gj = j0 + wn * 64 + nt * 8 + tig * 2;
            *(__half2*)(C + (size_t)gi * N_ + gj) =
                __floats2half2_rn(acc[mt][nt][0], acc[mt][nt][1]);
            *(__half2*)(C + (size_t)(gi + 8) * N_ + gj) =
                __floats2half2_rn(acc[mt][nt][2], acc[mt][nt][3]);
        }
    }
}

// GEMM2+3 fused with FFN epilogue; B loaded via trans path (no pre-transpose)
__global__ __launch_bounds__(256, 1) void gemm_dual_ffn(
    const __half* __restrict__ Sa, const __half* __restrict__ SbT,
    const __half* __restrict__ uc16, const __half* __restrict__ up16,
    const float* __restrict__ up, const float* __restrict__ uc,
    const float* __restrict__ W)
{
    __shared__ float red[8];
    int z = blockIdx.z;
    const __half* A = z ? SbT : Sa;
    const __half* B = z ? up16 : uc16;
    int i0 = blockIdx.y * 256, j0 = blockIdx.x * 128;
    float acc[4][8][4];
    gemm_compute<true>(A, B, D_, N_, 0, N_ / 64, i0, j0, acc);

    const int lane = threadIdx.x & 31, wid = threadIdx.x >> 5;
    const int wm = wid >> 1, wn = wid & 1;
    const int gid = lane >> 2, tig = lane & 3;
    const float* uin = z ? uc : up;
    float part = 0.f;
    #pragma unroll
    for (int mt = 0; mt < 4; mt++) {
        int gi0 = i0 + wm * 64 + mt * 16 + gid;
        #pragma unroll
        for (int r = 0; r < 2; r++) {
            int gi = gi0 + r * 8;
            const float* Wr = W + (size_t)gi * 4 * D_;
            #pragma unroll
            for (int nt = 0; nt < 8; nt++) {
                int gj = j0 + wn * 64 + nt * 8 + tig * 2;
                float a0 = acc[mt][nt][r * 2 + 0];
                float a1 = acc[mt][nt][r * 2 + 1];
                float2 uv = *(const float2*)(uin + (size_t)gi * D_ + gj);
                if (z == 0) {
                    float2 w1 = *(const float2*)(Wr + D_ + gj);
                    float2 w2 = *(const float2*)(Wr + 2 * D_ + gj);
                    part += a0 * (w1.x + uv.x * w2.x) + a1 * (w1.y + uv.y * w2.y);
                } else {
                    float2 w3 = *(const float2*)(Wr + 3 * D_ + gj);
                    part += a0 * uv.x * w3.x + a1 * uv.y * w3.y;
                }
            }
        }
    }
    part = warp_sum(part);
    if (lane == 0) red[wid] = part;
    __syncthreads();
    if (threadIdx.x == 0) {
        float tot = 0.f;
        #pragma unroll
        for (int i = 0; i < 8; i++) tot += red[i];
        g_ctapart[z * 64 + blockIdx.y * 16 + blockIdx.x] = tot;
    }
}

// ================= final scalar =================
__global__ void ffn_final(const float* __restrict__ b, float* __restrict__ out) {
    __shared__ float red[8];
    int t = threadIdx.x;
    float s = 0.f;
    for (int i = t; i < M_; i += 256) s += g_part[i];
    if (t < 128) s += g_ctapart[t];
    s = warp_sum(s);
    if ((t & 31) == 0) red[t >> 5] = s;
    __syncthreads();
    if (t == 0) {
        float tot = 0.f;
        #pragma unroll
        for (int i = 0; i < 8; i++) tot += red[i];
        out[0] = fmaxf(tot + b[0], 0.f);
    }
}

// ================= launch =================
extern "C" void kernel_launch(void* const* d_in, const int* in_sizes, int n_in,
                              void* d_out, int out_size) {
    const float* u_p   = (const float*)d_in[0];
    const float* u_c   = (const float*)d_in[1];
    const float* w_a   = (const float*)d_in[2];
    const float* ffn_w = (const float*)d_in[3];
    const float* ffn_b = (const float*)d_in[4];
    float* out = (float*)d_out;

    cudaFuncSetAttribute(gemm_splitk,   cudaFuncAttributeMaxDynamicSharedMemorySize, SMEM_GEMM);
    cudaFuncSetAttribute(gemm_dual_ffn, cudaFuncAttributeMaxDynamicSharedMemorySize, SMEM_GEMM);

    __half *vp16, *up16, *uc16, *Sa16, *SbT16, *Sp16;
    cudaGetSymbolAddress((void**)&vp16, g_vp16);
    cudaGetSymbolAddress((void**)&up16, g_up16);
    cudaGetSymbolAddress((void**)&uc16, g_uc16);
    cudaGetSymbolAddress((void**)&Sa16, g_Sa16);
    cudaGetSymbolAddress((void**)&SbT16, g_SbT16);
    cudaGetSymbolAddress((void**)&Sp16, g_Sp16);

    // K0: rp, rc, FFN term1, vp16, up16, uc16
    rv_kernel<<<M_ + N_, 256>>>(u_p, u_c, w_a, ffn_w);

    // GEMM1: fp16 S partials (split-K x4), then merge + bias + row softmax
    gemm_splitk<<<dim3(N_ / 128, M_ / 256, 4), 256, SMEM_GEMM>>>(vp16, uc16, Sp16);
    merge_rowsoftmax<<<M_, 256>>>();

    // col softmax stats + transposed Sb (fp16 S input)
    col_stats_part<<<dim3(N_ / 128, 8), dim3(128, 4)>>>();
    transpose_softmax16<<<dim3(N_ / 32, M_ / 32), dim3(32, 8)>>>();

    // GEMM2 + GEMM3 + FFN fused (trans-B, no pre-transposed operands)
    gemm_dual_ffn<<<dim3(D_ / 128, M_ / 256, 2), 256, SMEM_GEMM>>>(
        Sa16, SbT16, uc16, up16, u_p, u_c, ffn_w);

    // final scalar
    ffn_final<<<1, 256>>>(ffn_b, out);
}

// round 13
// speedup vs baseline: 2.5183x; 1.1284x over previous
#include <cuda_runtime.h>
#include <cuda_fp16.h>
#include <cstdint>
#include <math.h>

#define M_ 1024
#define N_ 1024
#define D_ 2048

// ================= helpers =================
__device__ __forceinline__ uint32_t smem_to_u32(const void* p) {
    uint32_t a;
    asm("{ .reg .u64 t; cvta.to.shared.u64 t, %1; cvt.u32.u64 %0, t; }" : "=r"(a) : "l"(p));
    return a;
}
#define SMEM_SWIZZLE_128B(b) ((b) ^ (((b) >> 3) & 0x70))

#define LDSM_X4(r, a) \
    asm volatile("ldmatrix.sync.aligned.m8n8.x4.shared.b16 {%0,%1,%2,%3}, [%4];" \
        : "=r"((r)[0]), "=r"((r)[1]), "=r"((r)[2]), "=r"((r)[3]) : "r"(a))
#define LDSM_X4_T(r, a) \
    asm volatile("ldmatrix.sync.aligned.m8n8.x4.trans.shared.b16 {%0,%1,%2,%3}, [%4];" \
        : "=r"((r)[0]), "=r"((r)[1]), "=r"((r)[2]), "=r"((r)[3]) : "r"(a))

__device__ __forceinline__ void mma_f16(float* c, const uint32_t* a, uint32_t b0, uint32_t b1) {
    asm volatile("mma.sync.aligned.m16n8k16.row.col.f32.f16.f16.f32 "
        "{%0,%1,%2,%3}, {%4,%5,%6,%7}, {%8,%9}, {%0,%1,%2,%3};"
        : "+f"(c[0]), "+f"(c[1]), "+f"(c[2]), "+f"(c[3])
        : "r"(a[0]), "r"(a[1]), "r"(a[2]), "r"(a[3]), "r"(b0), "r"(b1));
}

__device__ __forceinline__ float warp_sum(float v) {
    #pragma unroll
    for (int o = 16; o > 0; o >>= 1) v += __shfl_xor_sync(0xffffffffu, v, o);
    return v;
}

// ================= scratch =================
__device__ __half g_vp16[M_ * D_];
__device__ __half g_up16[M_ * D_];
__device__ __half g_uc16[N_ * D_];
__device__ __half g_Sa16[M_ * N_];
__device__ __half g_SbT16[N_ * M_];
__device__ __half g_Sp16[4 * M_ * N_];   // split-K partials (fp16)
__device__ __half g_E16[M_ * N_];        // E = exp(S) (fp16)
__device__ float g_rp[M_], g_rc[N_];
__device__ float g_psum[16 * N_];        // column partial sums of E
__device__ float g_part[M_];             // FFN term1 per row (u_p . W0)
__device__ float g_ctapart[128];         // FFN partials from dual CTAs

__device__ __forceinline__ void store_h4(__half* dst, size_t off, float4 v) {
    __half2 lo = __halves2half2(__float2half_rn(v.x), __float2half_rn(v.y));
    __half2 hi = __halves2half2(__float2half_rn(v.z), __float2half_rn(v.w));
    *(__half2*)(dst + off)     = lo;
    *(__half2*)(dst + off + 2) = hi;
}

// ================= K0: rp, rc, term1, vp16, up16, uc16 =================
__global__ void rv_kernel(const float* __restrict__ up, const float* __restrict__ uc,
                          const float* __restrict__ wa, const float* __restrict__ W) {
    __shared__ float sm1[8], sm2[8];
    int row = blockIdx.x, t = threadIdx.x;
    int w = t >> 5, l = t & 31;
    if (row < M_) {
        const float* a = up + (size_t)row * D_;
        const float* w1 = wa;
        const float* w3 = wa + 2 * D_;
        const float* W0 = W + (size_t)row * 4 * D_;
        float s = 0.f, s1 = 0.f;
        for (int k = t * 4; k < D_; k += 1024) {
            float4 av = *(const float4*)(a + k);
            float4 w1v = *(const float4*)(w1 + k);
            float4 w3v = *(const float4*)(w3 + k);
            float4 W0v = *(const float4*)(W0 + k);
            s += av.x * w1v.x + av.y * w1v.y + av.z * w1v.z + av.w * w1v.w;
            s1 += av.x * W0v.x + av.y * W0v.y + av.z * W0v.z + av.w * W0v.w;
            store_h4(g_vp16, (size_t)row * D_ + k,
                     make_float4(av.x * w3v.x, av.y * w3v.y, av.z * w3v.z, av.w * w3v.w));
            store_h4(g_up16, (size_t)row * D_ + k, av);
        }
        s = warp_sum(s); s1 = warp_sum(s1);
        if (l == 0) { sm1[w] = s; sm2[w] = s1; }
        __syncthreads();
        if (t == 0) {
            float a0 = 0.f, b0 = 0.f;
            #pragma unroll
            for (int i = 0; i < 8; i++) { a0 += sm1[i]; b0 += sm2[i]; }
            g_rp[row] = a0; g_part[row] = b0;
        }
    } else {
        int r2 = row - M_;
        const float* a = uc + (size_t)r2 * D_;
        const float* w2 = wa + D_;
        float s = 0.f;
        for (int k = t * 4; k < D_; k += 1024) {
            float4 av = *(const float4*)(a + k);
            float4 w2v = *(const float4*)(w2 + k);
            s += av.x * w2v.x + av.y * w2v.y + av.z * w2v.z + av.w * w2v.w;
            store_h4(g_uc16, (size_t)r2 * D_ + k, av);
        }
        s = warp_sum(s);
        if (l == 0) sm1[w] = s;
        __syncthreads();
        if (t == 0) {
            float a0 = 0.f;
            #pragma unroll
            for (int i = 0; i < 8; i++) a0 += sm1[i];
            g_rc[r2] = a0;
        }
    }
}

// ================= merge partials + bias + E=exp(S) + row softmax =================
__global__ void merge_rowsoftmax() {
    __shared__ float ssm[8];
    int row = blockIdx.x, t = threadIdx.x;
    int w = t >> 5, l = t & 31;
    float rpv = g_rp[row];
    int j = t * 4;
    float4 rc4 = *(const float4*)(g_rc + j);
    float4 o = make_float4(rpv + rc4.x, rpv + rc4.y, rpv + rc4.z, rpv + rc4.w);
    #pragma unroll
    for (int z = 0; z < 4; z++) {
        const __half* P = g_Sp16 + (size_t)z * M_ * N_ + (size_t)row * N_ + j;
        float2 f01 = __half22float2(*(const __half2*)(P));
        float2 f23 = __half22float2(*(const __half2*)(P + 2));
        o.x += f01.x; o.y += f01.y; o.z += f23.x; o.w += f23.y;
    }
    // E = exp(S) (no max subtraction: |S| small); shared by row AND col softmax
    float e0 = __expf(o.x), e1 = __expf(o.y);
    float e2 = __expf(o.z), e3 = __expf(o.w);
    store_h4(g_E16, (size_t)row * N_ + j, make_float4(e0, e1, e2, e3));

    float s = warp_sum(e0 + e1 + e2 + e3);
    if (l == 0) ssm[w] = s;
    __syncthreads();
    s = ssm[0];
    #pragma unroll
    for (int i = 1; i < 8; i++) s += ssm[i];
    float inv = 1.0f / s;
    store_h4(g_Sa16, (size_t)row * N_ + j,
             make_float4(e0 * inv, e1 * inv, e2 * inv, e3 * inv));
}

// ================= column sums of E (plain adds, no exp) =================
__global__ void col_sum() {
    // grid (N_/128, 16), block (128, 4): 64 rows per block, 16 per thread
    int tx = threadIdx.x, ty = threadIdx.y;
    int c = blockIdx.x * 128 + tx;
    int r0 = blockIdx.y * 64;
    float s0 = 0.f, s1 = 0.f;
    #pragma unroll
    for (int jj = 0; jj < 16; jj += 2) {
        s0 += __half2float(g_E16[(size_t)(r0 + ty + jj * 4) * N_ + c]);
        s1 += __half2float(g_E16[(size_t)(r0 + ty + (jj + 1) * 4) * N_ + c]);
    }
    __shared__ float sm[4][128];
    sm[ty][tx] = s0 + s1;
    __syncthreads();
    if (ty == 0)
        g_psum[blockIdx.y * N_ + c] = sm[0][tx] + sm[1][tx] + sm[2][tx] + sm[3][tx];
}

// transpose E and scale by column inverse sum (no exp)
__global__ void transpose_scale16() {
    __shared__ float t[32][33];
    __shared__ float civ[32];
    int tx = threadIdx.x, ty = threadIdx.y;
    int r0 = blockIdx.y * 32, c0 = blockIdx.x * 32;
    if (ty == 0) {
        int c = c0 + tx;
        float s = 0.f;
        #pragma unroll
        for (int k = 0; k < 16; k++) s += g_psum[k * N_ + c];
        civ[tx] = 1.0f / s;
    }
    __syncthreads();
    float ci = civ[tx];
    #pragma unroll
    for (int j = 0; j < 4; j++) {
        float v = __half2float(g_E16[(size_t)(r0 + ty + j * 8) * N_ + c0 + tx]);
        t[ty + j * 8][tx] = v * ci;
    }
    __syncthreads();
    #pragma unroll
    for (int j = 0; j < 4; j++) {
        int c = c0 + ty + j * 8;
        g_SbT16[(size_t)c * M_ + r0 + tx] = __float2half_rn(t[tx][ty + j * 8]);
    }
}

// ================= fp16 mma GEMM core: 256x128 tile, warp tile 64x64 =================
#define NSTG 4
#define TILE_A_SZ 32768
#define TILE_B_SZ 16384
#define SMEM_GEMM (NSTG * (TILE_A_SZ + TILE_B_SZ))   // 196608

__device__ __forceinline__ void cp_tileA(uint32_t sdst, const __half* src,
                                         int row0, int ld, int k0, int tid) {
    const char* gb = (const char*)(src + (size_t)row0 * ld + k0);
    size_t rb = (size_t)ld * 2;
    #pragma unroll
    for (int it = 0; it < 8; it++) {
        int idx = tid + it * 256;
        int r = idx >> 3;
        int cb = (idx & 7) << 4;
        const void* g = gb + (size_t)r * rb + cb;
        uint32_t s = sdst + SMEM_SWIZZLE_128B(r * 128 + cb);
        asm volatile("cp.async.cg.shared.global [%0], [%1], 16;" :: "r"(s), "l"(g));
    }
}
__device__ __forceinline__ void cp_tileB(uint32_t sdst, const __half* src,
                                         int row0, int ld, int k0, int tid) {
    const char* gb = (const char*)(src + (size_t)row0 * ld + k0);
    size_t rb = (size_t)ld * 2;
    #pragma unroll
    for (int it = 0; it < 4; it++) {
        int idx = tid + it * 256;
        int r = idx >> 3;
        int cb = (idx & 7) << 4;
        const void* g = gb + (size_t)r * rb + cb;
        uint32_t s = sdst + SMEM_SWIZZLE_128B(r * 128 + cb);
        asm volatile("cp.async.cg.shared.global [%0], [%1], 16;" :: "r"(s), "l"(g));
    }
}
// trans B: 64 k-rows x 128 j-cols fp16 (256B gmem rows) -> two 64x128B swizzled segments
__device__ __forceinline__ void cp_tileB_trans(uint32_t sdst, const __half* src,
                                               int krow0, int ld, int j0, int tid) {
    const char* gb = (const char*)(src + (size_t)krow0 * ld + j0);
    size_t rb = (size_t)ld * 2;
    #pragma unroll
    for (int it = 0; it < 4; it++) {
        int idx = tid + it * 256;
        int r = idx >> 4;
        int c16 = idx & 15;
        const void* g = gb + (size_t)r * rb + c16 * 16;
        uint32_t off = ((uint32_t)(c16 >> 3) << 13) + ((uint32_t)r << 7) + ((c16 & 7) << 4);
        uint32_t s = sdst + SMEM_SWIZZLE_128B(off);
        asm volatile("cp.async.cg.shared.global [%0], [%1], 16;" :: "r"(s), "l"(g));
    }
}

template<bool TB>
__device__ __forceinline__ void gemm_compute(
    const __half* __restrict__ A, const __half* __restrict__ B, int ldB,
    int Kdim, int c0, int ncl, int i0, int j0,
    float (&acc)[4][8][4])
{
    extern __shared__ __align__(1024) char smem[];
    uint32_t sb = smem_to_u32(smem);
    const int tid = threadIdx.x;
    const int wid = tid >> 5, lane = tid & 31;
    const int wm = wid >> 1, wn = wid & 1;

    #pragma unroll
    for (int a = 0; a < 4; a++)
        #pragma unroll
        for (int b = 0; b < 8; b++)
            #pragma unroll
            for (int c = 0; c < 4; c++) acc[a][b][c] = 0.f;

    uint32_t cA = (uint32_t)((wm * 64 + (lane & 15)) << 7) + ((lane >> 4) << 4);
    cA ^= ((cA >> 3) & 0x70);
    uint32_t cB;
    if (TB) {
        uint32_t kr = (lane & 7) + (((lane >> 3) & 1) << 3);
        uint32_t jc = ((lane >> 4) & 1) << 3;
        cB = ((uint32_t)wn << 13) + (kr << 7) + (jc << 1);
        cB ^= ((cB >> 3) & 0x70);
    } else {
        uint32_t rowB = (lane & 7) + ((lane >> 4) << 3);
        cB = (uint32_t)((wn * 64 + rowB) << 7) + (((lane >> 3) & 1) << 4);
        cB ^= ((cB >> 3) & 0x70);
    }

    #define STG_A(s) (sb + (s) * (TILE_A_SZ + TILE_B_SZ))
    #define STG_B(s) (sb + (s) * (TILE_A_SZ + TILE_B_SZ) + TILE_A_SZ)
    #define LOAD_CHUNK(st, ci) do { \
        cp_tileA(STG_A(st), A, i0, Kdim, (ci) * 64, tid); \
        if (TB) cp_tileB_trans(STG_B(st), B, (ci) * 64, ldB, j0, tid); \
        else    cp_tileB(STG_B(st), B, j0, ldB, (ci) * 64, tid); \
    } while (0)

    LOAD_CHUNK(0, c0);
    asm volatile("cp.async.commit_group;" ::: "memory");
    LOAD_CHUNK(1, c0 + 1);
    asm volatile("cp.async.commit_group;" ::: "memory");

    for (int li = 0; li < ncl; li++) {
        int s = li & 3;
        asm volatile("cp.async.wait_group 1;" ::: "memory");
        __syncthreads();
        if (li + 2 < ncl) LOAD_CHUNK((li + 2) & 3, c0 + li + 2);
        asm volatile("cp.async.commit_group;" ::: "memory");

        uint32_t aBase = STG_A(s) + cA;
        uint32_t bBase = STG_B(s) + cB;
        #pragma unroll
        for (int ks = 0; ks < 4; ks++) {
            uint32_t afr[4][4], bfr[4][4];
            #pragma unroll
            for (int mt = 0; mt < 4; mt++)
                LDSM_X4(afr[mt], (aBase + mt * 2048) ^ (ks << 5));
            #pragma unroll
            for (int p = 0; p < 4; p++) {
                if (TB) LDSM_X4_T(bfr[p], (bBase + ks * 2048) ^ (p << 5));
                else    LDSM_X4(bfr[p], (bBase + p * 2048) ^ (ks << 5));
            }
            #pragma unroll
            for (int mt = 0; mt < 4; mt++) {
                #pragma unroll
                for (int p = 0; p < 4; p++) {
                    mma_f16(acc[mt][p * 2 + 0], afr[mt], bfr[p][0], bfr[p][1]);
                    mma_f16(acc[mt][p * 2 + 1], afr[mt], bfr[p][2], bfr[p][3]);
                }
            }
        }
    }
    #undef STG_A
    #undef STG_B
    #undef LOAD_CHUNK
}

// GEMM1: S partials = vp16 @ uc16^T, split-K x4, fp16 partial output
__global__ __launch_bounds__(256, 1) void gemm_splitk(
    const __half* __restrict__ A, const __half* __restrict__ B, __half* __restrict__ Cp)
{
    int z = blockIdx.z;
    const int q = (D_ / 64) / 4;
    int i0 = blockIdx.y * 256, j0 = blockIdx.x * 128;
    float acc[4][8][4];
    gemm_compute<false>(A, B, D_, D_, z * q, q, i0, j0, acc);

    const int lane = threadIdx.x & 31, wid = threadIdx.x >> 5;
    const int wm = wid >> 1, wn = wid & 1;
    const int gid = lane >> 2, tig = lane & 3;
    __half* C = Cp + (size_t)z * M_ * N_;
    #pragma unroll
    for (int mt = 0; mt < 4; mt++) {
        int gi = i0 + wm * 64 + mt * 16 + gid;
        #pragma unroll
        for (int nt = 0; nt < 8; nt++) {
            int gj = j0 + wn * 64 + nt * 8 + tig * 2;
            *(__half2*)(C + (size_t)gi * N_ + gj) =
                __floats2half2_rn(acc[mt][nt][0], acc[mt][nt][1]);
            *(__half2*)(C + (size_t)(gi + 8) * N_ + gj) =
                __floats2half2_rn(acc[mt][nt][2], acc[mt][nt][3]);
        }
    }
}

// GEMM2+3 fused with FFN epilogue; B via trans path
__global__ __launch_bounds__(256, 1) void gemm_dual_ffn(
    const __half* __restrict__ Sa, const __half* __restrict__ SbT,
    const __half* __restrict__ uc16, const __half* __restrict__ up16,
    const float* __restrict__ up, const float* __restrict__ uc,
    const float* __restrict__ W)
{
    __shared__ float red[8];
    int z = blockIdx.z;
    const __half* A = z ? SbT : Sa;
    const __half* B = z ? up16 : uc16;
    int i0 = blockIdx.y * 256, j0 = blockIdx.x * 128;
    float acc[4][8][4];
    gemm_compute<true>(A, B, D_, N_, 0, N_ / 64, i0, j0, acc);

    const int lane = threadIdx.x & 31, wid = threadIdx.x >> 5;
    const int wm = wid >> 1, wn = wid & 1;
    const int gid = lane >> 2, tig = lane & 3;
    const float* uin = z ? uc : up;
    float part = 0.f;
    #pragma unroll
    for (int mt = 0; mt < 4; mt++) {
        int gi0 = i0 + wm * 64 + mt * 16 + gid;
        #pragma unroll
        for (int r = 0; r < 2; r++) {
            int gi = gi0 + r * 8;
            const float* Wr = W + (size_t)gi * 4 * D_;
            #pragma unroll
            for (int nt = 0; nt < 8; nt++) {
                int gj = j0 + wn * 64 + nt * 8 + tig * 2;
                float a0 = acc[mt][nt][r * 2 + 0];
                float a1 = acc[mt][nt][r * 2 + 1];
                float2 uv = *(const float2*)(uin + (size_t)gi * D_ + gj);
                if (z == 0) {
                    float2 w1 = *(const float2*)(Wr + D_ + gj);
                    float2 w2 = *(const float2*)(Wr + 2 * D_ + gj);
                    part += a0 * (w1.x + uv.x * w2.x) + a1 * (w1.y + uv.y * w2.y);
                } else {
                    float2 w3 = *(const float2*)(Wr + 3 * D_ + gj);
                    part += a0 * uv.x * w3.x + a1 * uv.y * w3.y;
                }
            }
        }
    }
    part = warp_sum(part);
    if (lane == 0) red[wid] = part;
    __syncthreads();
    if (threadIdx.x == 0) {
        float tot = 0.f;
        #pragma unroll
        for (int i = 0; i < 8; i++) tot += red[i];
        g_ctapart[z * 64 + blockIdx.y * 16 + blockIdx.x] = tot;
    }
}

// ================= final scalar =================
__global__ void ffn_final(const float* __restrict__ b, float* __restrict__ out) {
    __shared__ float red[8];
    int t = threadIdx.x;
    float s = 0.f;
    for (int i = t; i < M_; i += 256) s += g_part[i];
    if (t < 128) s += g_ctapart[t];
    s = warp_sum(s);
    if ((t & 31) == 0) red[t >> 5] = s;
    __syncthreads();
    if (t == 0) {
        float tot = 0.f;
        #pragma unroll
        for (int i = 0; i < 8; i++) tot += red[i];
        out[0] = fmaxf(tot + b[0], 0.f);
    }
}

// ================= launch =================
extern "C" void kernel_launch(void* const* d_in, const int* in_sizes, int n_in,
                              void* d_out, int out_size) {
    const float* u_p   = (const float*)d_in[0];
    const float* u_c   = (const float*)d_in[1];
    const float* w_a   = (const float*)d_in[2];
    const float* ffn_w = (const float*)d_in[3];
    const float* ffn_b = (const float*)d_in[4];
    float* out = (float*)d_out;

    cudaFuncSetAttribute(gemm_splitk,   cudaFuncAttributeMaxDynamicSharedMemorySize, SMEM_GEMM);
    cudaFuncSetAttribute(gemm_dual_ffn, cudaFuncAttributeMaxDynamicSharedMemorySize, SMEM_GEMM);

    __half *vp16, *up16, *uc16, *Sa16, *SbT16, *Sp16;
    cudaGetSymbolAddress((void**)&vp16, g_vp16);
    cudaGetSymbolAddress((void**)&up16, g_up16);
    cudaGetSymbolAddress((void**)&uc16, g_uc16);
    cudaGetSymbolAddress((void**)&Sa16, g_Sa16);
    cudaGetSymbolAddress((void**)&SbT16, g_SbT16);
    cudaGetSymbolAddress((void**)&Sp16, g_Sp16);

    // K0: rp, rc, FFN term1, vp16, up16, uc16
    rv_kernel<<<M_ + N_, 256>>>(u_p, u_c, w_a, ffn_w);

    // GEMM1: fp16 S partials (split-K x4), then merge + E=exp(S) + row softmax
    gemm_splitk<<<dim3(N_ / 128, M_ / 256, 4), 256, SMEM_GEMM>>>(vp16, uc16, Sp16);
    merge_rowsoftmax<<<M_, 256>>>();

    // column sums of E + transpose-scale (no exps)
    col_sum<<<dim3(N_ / 128, 16), dim3(128, 4)>>>();
    transpose_scale16<<<dim3(N_ / 32, M_ / 32), dim3(32, 8)>>>();

    // GEMM2 + GEMM3 + FFN fused (trans-B)
    gemm_dual_ffn<<<dim3(D_ / 128, M_ / 256, 2), 256, SMEM_GEMM>>>(
        Sa16, SbT16, uc16, up16, u_p, u_c, ffn_w);

    // final scalar
    ffn_final<<<1, 256>>>(ffn_b, out);
}

// round 14
// speedup vs baseline: 2.7082x; 1.0754x over previous
#include <cuda_runtime.h>
#include <cuda_fp16.h>
#include <cstdint>
#include <math.h>

#define M_ 1024
#define N_ 1024
#define D_ 2048

// ================= helpers =================
__device__ __forceinline__ uint32_t smem_to_u32(const void* p) {
    uint32_t a;
    asm("{ .reg .u64 t; cvta.to.shared.u64 t, %1; cvt.u32.u64 %0, t; }" : "=r"(a) : "l"(p));
    return a;
}
#define SMEM_SWIZZLE_128B(b) ((b) ^ (((b) >> 3) & 0x70))

#define LDSM_X4(r, a) \
    asm volatile("ldmatrix.sync.aligned.m8n8.x4.shared.b16 {%0,%1,%2,%3}, [%4];" \
        : "=r"((r)[0]), "=r"((r)[1]), "=r"((r)[2]), "=r"((r)[3]) : "r"(a))
#define LDSM_X4_T(r, a) \
    asm volatile("ldmatrix.sync.aligned.m8n8.x4.trans.shared.b16 {%0,%1,%2,%3}, [%4];" \
        : "=r"((r)[0]), "=r"((r)[1]), "=r"((r)[2]), "=r"((r)[3]) : "r"(a))

__device__ __forceinline__ void mma_f16(float* c, const uint32_t* a, uint32_t b0, uint32_t b1) {
    asm volatile("mma.sync.aligned.m16n8k16.row.col.f32.f16.f16.f32 "
        "{%0,%1,%2,%3}, {%4,%5,%6,%7}, {%8,%9}, {%0,%1,%2,%3};"
        : "+f"(c[0]), "+f"(c[1]), "+f"(c[2]), "+f"(c[3])
        : "r"(a[0]), "r"(a[1]), "r"(a[2]), "r"(a[3]), "r"(b0), "r"(b1));
}

__device__ __forceinline__ float warp_sum(float v) {
    #pragma unroll
    for (int o = 16; o > 0; o >>= 1) v += __shfl_xor_sync(0xffffffffu, v, o);
    return v;
}

// ================= scratch =================
__device__ __half g_vp16[M_ * D_];
__device__ __half g_up16[M_ * D_];
__device__ __half g_uc16[N_ * D_];
__device__ __half g_Sp16[4 * M_ * N_];   // split-K partials (fp16)
__device__ __half g_E16[M_ * N_];        // E = exp(S) (fp16)
__device__ float g_rp[M_], g_rc[N_];
__device__ float g_rinv[M_];             // 1 / rowsum(E)
__device__ float g_psum[32 * N_];        // column partial sums of E (32 strips)
__device__ float g_part[M_];             // FFN term1 per row (u_p . W0)
__device__ float g_ctapart[128];         // FFN partials from dual CTAs

__device__ __forceinline__ void store_h4(__half* dst, size_t off, float4 v) {
    __half2 lo = __halves2half2(__float2half_rn(v.x), __float2half_rn(v.y));
    __half2 hi = __halves2half2(__float2half_rn(v.z), __float2half_rn(v.w));
    *(__half2*)(dst + off)     = lo;
    *(__half2*)(dst + off + 2) = hi;
}

// ================= K0: rp, rc, term1, vp16, up16, uc16 =================
__global__ void rv_kernel(const float* __restrict__ up, const float* __restrict__ uc,
                          const float* __restrict__ wa, const float* __restrict__ W) {
    __shared__ float sm1[8], sm2[8];
    int row = blockIdx.x, t = threadIdx.x;
    int w = t >> 5, l = t & 31;
    if (row < M_) {
        const float* a = up + (size_t)row * D_;
        const float* w1 = wa;
        const float* w3 = wa + 2 * D_;
        const float* W0 = W + (size_t)row * 4 * D_;
        float s = 0.f, s1 = 0.f;
        for (int k = t * 4; k < D_; k += 1024) {
            float4 av = *(const float4*)(a + k);
            float4 w1v = *(const float4*)(w1 + k);
            float4 w3v = *(const float4*)(w3 + k);
            float4 W0v = *(const float4*)(W0 + k);
            s += av.x * w1v.x + av.y * w1v.y + av.z * w1v.z + av.w * w1v.w;
            s1 += av.x * W0v.x + av.y * W0v.y + av.z * W0v.z + av.w * W0v.w;
            store_h4(g_vp16, (size_t)row * D_ + k,
                     make_float4(av.x * w3v.x, av.y * w3v.y, av.z * w3v.z, av.w * w3v.w));
            store_h4(g_up16, (size_t)row * D_ + k, av);
        }
        s = warp_sum(s); s1 = warp_sum(s1);
        if (l == 0) { sm1[w] = s; sm2[w] = s1; }
        __syncthreads();
        if (t == 0) {
            float a0 = 0.f, b0 = 0.f;
            #pragma unroll
            for (int i = 0; i < 8; i++) { a0 += sm1[i]; b0 += sm2[i]; }
            g_rp[row] = a0; g_part[row] = b0;
        }
    } else {
        int r2 = row - M_;
        const float* a = uc + (size_t)r2 * D_;
        const float* w2 = wa + D_;
        float s = 0.f;
        for (int k = t * 4; k < D_; k += 1024) {
            float4 av = *(const float4*)(a + k);
            float4 w2v = *(const float4*)(w2 + k);
            s += av.x * w2v.x + av.y * w2v.y + av.z * w2v.z + av.w * w2v.w;
            store_h4(g_uc16, (size_t)r2 * D_ + k, av);
        }
        s = warp_sum(s);
        if (l == 0) sm1[w] = s;
        __syncthreads();
        if (t == 0) {
            float a0 = 0.f;
            #pragma unroll
            for (int i = 0; i < 8; i++) a0 += sm1[i];
            g_rc[r2] = a0;
        }
    }
}

// ================= merge partials + bias + E=exp(S) + rowsum inverse =================
__global__ void merge_exp() {
    __shared__ float ssm[8];
    int row = blockIdx.x, t = threadIdx.x;
    int w = t >> 5, l = t & 31;
    float rpv = g_rp[row];
    int j = t * 4;
    float4 rc4 = *(const float4*)(g_rc + j);
    float4 o = make_float4(rpv + rc4.x, rpv + rc4.y, rpv + rc4.z, rpv + rc4.w);
    #pragma unroll
    for (int z = 0; z < 4; z++) {
        const __half* P = g_Sp16 + (size_t)z * M_ * N_ + (size_t)row * N_ + j;
        float2 f01 = __half22float2(*(const __half2*)(P));
        float2 f23 = __half22float2(*(const __half2*)(P + 2));
        o.x += f01.x; o.y += f01.y; o.z += f23.x; o.w += f23.y;
    }
    float e0 = __expf(o.x), e1 = __expf(o.y);
    float e2 = __expf(o.z), e3 = __expf(o.w);
    store_h4(g_E16, (size_t)row * N_ + j, make_float4(e0, e1, e2, e3));

    float s = warp_sum(e0 + e1 + e2 + e3);
    if (l == 0) ssm[w] = s;
    __syncthreads();
    if (t == 0) {
        float tot = 0.f;
        #pragma unroll
        for (int i = 0; i < 8; i++) tot += ssm[i];
        g_rinv[row] = 1.0f / tot;
    }
}

// ================= column partial sums of E (32 strips of 32 rows) =================
__global__ void col_sum() {
    int tx = threadIdx.x, ty = threadIdx.y;
    int c = blockIdx.x * 128 + tx;
    int r0 = blockIdx.y * 32;
    float s0 = 0.f, s1 = 0.f;
    #pragma unroll
    for (int jj = 0; jj < 8; jj += 2) {
        s0 += __half2float(g_E16[(size_t)(r0 + ty + jj * 4) * N_ + c]);
        s1 += __half2float(g_E16[(size_t)(r0 + ty + (jj + 1) * 4) * N_ + c]);
    }
    __shared__ float sm[4][128];
    sm[ty][tx] = s0 + s1;
    __syncthreads();
    if (ty == 0)
        g_psum[blockIdx.y * N_ + c] = sm[0][tx] + sm[1][tx] + sm[2][tx] + sm[3][tx];
}

// ================= fp16 mma GEMM core: 256x128 tile, warp tile 64x64 =================
#define NSTG 4
#define TILE_A_SZ 32768
#define TILE_B_SZ 16384
#define SMEM_GEMM (NSTG * (TILE_A_SZ + TILE_B_SZ))   // 196608

__device__ __forceinline__ void cp_tileA(uint32_t sdst, const __half* src,
                                         int row0, int ld, int k0, int tid) {
    const char* gb = (const char*)(src + (size_t)row0 * ld + k0);
    size_t rb = (size_t)ld * 2;
    #pragma unroll
    for (int it = 0; it < 8; it++) {
        int idx = tid + it * 256;
        int r = idx >> 3;
        int cb = (idx & 7) << 4;
        const void* g = gb + (size_t)r * rb + cb;
        uint32_t s = sdst + SMEM_SWIZZLE_128B(r * 128 + cb);
        asm volatile("cp.async.cg.shared.global [%0], [%1], 16;" :: "r"(s), "l"(g));
    }
}
// trans A: 64 k-rows x 256 m-cols -> four 64x128B swizzled segments
__device__ __forceinline__ void cp_tileA_trans(uint32_t sdst, const __half* src,
                                               int krow0, int ld, int m0, int tid) {
    const char* gb = (const char*)(src + (size_t)krow0 * ld + m0);
    size_t rb = (size_t)ld * 2;
    #pragma unroll
    for (int it = 0; it < 8; it++) {
        int idx = tid + it * 256;
        int r = idx >> 5;             // k-row 0..63
        int c16 = idx & 31;           // 16B chunk (8 m-values)
        const void* g = gb + (size_t)r * rb + c16 * 16;
        uint32_t off = ((uint32_t)(c16 >> 3) << 13) + ((uint32_t)r << 7) + ((c16 & 7) << 4);
        uint32_t s = sdst + SMEM_SWIZZLE_128B(off);
        asm volatile("cp.async.cg.shared.global [%0], [%1], 16;" :: "r"(s), "l"(g));
    }
}
__device__ __forceinline__ void cp_tileB(uint32_t sdst, const __half* src,
                                         int row0, int ld, int k0, int tid) {
    const char* gb = (const char*)(src + (size_t)row0 * ld + k0);
    size_t rb = (size_t)ld * 2;
    #pragma unroll
    for (int it = 0; it < 4; it++) {
        int idx = tid + it * 256;
        int r = idx >> 3;
        int cb = (idx & 7) << 4;
        const void* g = gb + (size_t)r * rb + cb;
        uint32_t s = sdst + SMEM_SWIZZLE_128B(r * 128 + cb);
        asm volatile("cp.async.cg.shared.global [%0], [%1], 16;" :: "r"(s), "l"(g));
    }
}
// trans B: 64 k-rows x 128 j-cols -> two 64x128B swizzled segments
__device__ __forceinline__ void cp_tileB_trans(uint32_t sdst, const __half* src,
                                               int krow0, int ld, int j0, int tid) {
    const char* gb = (const char*)(src + (size_t)krow0 * ld + j0);
    size_t rb = (size_t)ld * 2;
    #pragma unroll
    for (int it = 0; it < 4; it++) {
        int idx = tid + it * 256;
        int r = idx >> 4;
        int c16 = idx & 15;
        const void* g = gb + (size_t)r * rb + c16 * 16;
        uint32_t off = ((uint32_t)(c16 >> 3) << 13) + ((uint32_t)r << 7) + ((c16 & 7) << 4);
        uint32_t s = sdst + SMEM_SWIZZLE_128B(off);
        asm volatile("cp.async.cg.shared.global [%0], [%1], 16;" :: "r"(s), "l"(g));
    }
}

// warp grid 4x2 (wm=wid>>1, wn=wid&1), warp tile 64x64, acc[4(mt)][8(nt)][4]
// TA: A stored k-major (A = E^T case) via ldmatrix.trans. TB: B stored k-major.
template<bool TA, bool TB>
__device__ __forceinline__ void gemm_compute(
    const __half* __restrict__ A, int ldA,
    const __half* __restrict__ B, int ldB,
    int c0, int ncl, int i0, int j0,
    float (&acc)[4][8][4])
{
    extern __shared__ __align__(1024) char smem[];
    uint32_t sb = smem_to_u32(smem);
    const int tid = threadIdx.x;
    const int wid = tid >> 5, lane = tid & 31;
    const int wm = wid >> 1, wn = wid & 1;

    #pragma unroll
    for (int a = 0; a < 4; a++)
        #pragma unroll
        for (int b = 0; b < 8; b++)
            #pragma unroll
            for (int c = 0; c < 4; c++) acc[a][b][c] = 0.f;

    uint32_t cA = 0, cAt[4];
    if (TA) {
        // trans-A fragment addressing: reg q -> tile {m0-7,k0-7},{m8-15,k0-7},{m0-7,k8-15},{m8-15,k8-15}
        uint32_t q = lane >> 3, rowt = lane & 7;
        uint32_t kr = ((q >> 1) & 1) * 8 + rowt;           // 0..15
        #pragma unroll
        for (int mt = 0; mt < 4; mt++) {
            uint32_t mof = (uint32_t)(wm * 64 + mt * 16) + (q & 1) * 8;   // 0..255
            uint32_t off = ((mof >> 6) << 13) + (kr << 7) + ((mof & 63) << 1);
            cAt[mt] = SMEM_SWIZZLE_128B(off);
        }
    } else {
        cA = (uint32_t)((wm * 64 + (lane & 15)) << 7) + ((lane >> 4) << 4);
        cA ^= ((cA >> 3) & 0x70);
    }
    uint32_t cB;
    if (TB) {
        uint32_t kr = (lane & 7) + (((lane >> 3) & 1) << 3);
        uint32_t jc = ((lane >> 4) & 1) << 3;
        cB = ((uint32_t)wn << 13) + (kr << 7) + (jc << 1);
        cB ^= ((cB >> 3) & 0x70);
    } else {
        uint32_t rowB = (lane & 7) + ((lane >> 4) << 3);
        cB = (uint32_t)((wn * 64 + rowB) << 7) + (((lane >> 3) & 1) << 4);
        cB ^= ((cB >> 3) & 0x70);
    }

    #define STG_A(s) (sb + (s) * (TILE_A_SZ + TILE_B_SZ))
    #define STG_B(s) (sb + (s) * (TILE_A_SZ + TILE_B_SZ) + TILE_A_SZ)
    #define LOAD_CHUNK(st, ci) do { \
        if (TA) cp_tileA_trans(STG_A(st), A, (ci) * 64, ldA, i0, tid); \
        else    cp_tileA(STG_A(st), A, i0, ldA, (ci) * 64, tid); \
        if (TB) cp_tileB_trans(STG_B(st), B, (ci) * 64, ldB, j0, tid); \
        else    cp_tileB(STG_B(st), B, j0, ldB, (ci) * 64, tid); \
    } while (0)

    LOAD_CHUNK(0, c0);
    asm volatile("cp.async.commit_group;" ::: "memory");
    LOAD_CHUNK(1, c0 + 1);
    asm volatile("cp.async.commit_group;" ::: "memory");

    for (int li = 0; li < ncl; li++) {
        int s = li & 3;
        asm volatile("cp.async.wait_group 1;" ::: "memory");
        __syncthreads();
        if (li + 2 < ncl) LOAD_CHUNK((li + 2) & 3, c0 + li + 2);
        asm volatile("cp.async.commit_group;" ::: "memory");

        uint32_t aBase = STG_A(s) + cA;
        uint32_t bBase = STG_B(s) + cB;
        #pragma unroll
        for (int ks = 0; ks < 4; ks++) {
            uint32_t afr[4][4], bfr[4][4];
            #pragma unroll
            for (int mt = 0; mt < 4; mt++) {
                if (TA) LDSM_X4_T(afr[mt], STG_A(s) + cAt[mt] + ks * 2048);
                else    LDSM_X4(afr[mt], (aBase + mt * 2048) ^ (ks << 5));
            }
            #pragma unroll
            for (int p = 0; p < 4; p++) {
                if (TB) LDSM_X4_T(bfr[p], (bBase + ks * 2048) ^ (p << 5));
                else    LDSM_X4(bfr[p], (bBase + p * 2048) ^ (ks << 5));
            }
            #pragma unroll
            for (int mt = 0; mt < 4; mt++) {
                #pragma unroll
                for (int p = 0; p < 4; p++) {
                    mma_f16(acc[mt][p * 2 + 0], afr[mt], bfr[p][0], bfr[p][1]);
                    mma_f16(acc[mt][p * 2 + 1], afr[mt], bfr[p][2], bfr[p][3]);
                }
            }
        }
    }
    #undef STG_A
    #undef STG_B
    #undef LOAD_CHUNK
}

// GEMM1: S partials = vp16 @ uc16^T, split-K x4, fp16 partial output
__global__ __launch_bounds__(256, 1) void gemm_splitk(
    const __half* __restrict__ A, const __half* __restrict__ B, __half* __restrict__ Cp)
{
    int z = blockIdx.z;
    const int q = (D_ / 64) / 4;
    int i0 = blockIdx.y * 256, j0 = blockIdx.x * 128;
    float acc[4][8][4];
    gemm_compute<false, false>(A, D_, B, D_, z * q, q, i0, j0, acc);

    const int lane = threadIdx.x & 31, wid = threadIdx.x >> 5;
    const int wm = wid >> 1, wn = wid & 1;
    const int gid = lane >> 2, tig = lane & 3;
    __half* C = Cp + (size_t)z * M_ * N_;
    #pragma unroll
    for (int mt = 0; mt < 4; mt++) {
        int gi = i0 + wm * 64 + mt * 16 + gid;
        #pragma unroll
        for (int nt = 0; nt < 8; nt++) {
            int gj = j0 + wn * 64 + nt * 8 + tig * 2;
            *(__half2*)(C + (size_t)gi * N_ + gj) =
                __floats2half2_rn(acc[mt][nt][0], acc[mt][nt][1]);
            *(__half2*)(C + (size_t)(gi + 8) * N_ + gj) =
                __floats2half2_rn(acc[mt][nt][2], acc[mt][nt][3]);
        }
    }
}

// GEMM2+3 fused with FFN epilogue. A = E (z=0, non-trans) or E^T (z=1, trans-A).
// Softmax normalization applied as per-row scalar in the epilogue.
__global__ __launch_bounds__(256, 1) void gemm_dual_ffn(
    const __half* __restrict__ E,
    const __half* __restrict__ uc16, const __half* __restrict__ up16,
    const float* __restrict__ up, const float* __restrict__ uc,
    const float* __restrict__ W)
{
    __shared__ float red[8];
    __shared__ float scale[256];
    int z = blockIdx.z;
    int i0 = blockIdx.y * 256, j0 = blockIdx.x * 128;
    float acc[4][8][4];
    if (z == 0)
        gemm_compute<false, true>(E, N_, uc16, D_, 0, N_ / 64, i0, j0, acc);
    else
        gemm_compute<true, true>(E, N_, up16, D_, 0, M_ / 64, i0, j0, acc);

    // per-row normalization scale
    {
        int i = threadIdx.x;
        if (z == 0) {
            scale[i] = g_rinv[i0 + i];
        } else {
            float s = 0.f;
            #pragma unroll
            for (int k = 0; k < 32; k++) s += g_psum[k * N_ + i0 + i];
            scale[i] = 1.0f / s;
        }
    }
    __syncthreads();

    const int lane = threadIdx.x & 31, wid = threadIdx.x >> 5;
    const int wm = wid >> 1, wn = wid & 1;
    const int gid = lane >> 2, tig = lane & 3;
    const float* uin = z ? uc : up;
    float part = 0.f;
    #pragma unroll
    for (int mt = 0; mt < 4; mt++) {
        int li0 = wm * 64 + mt * 16 + gid;
        #pragma unroll
        for (int r = 0; r < 2; r++) {
            int gi = i0 + li0 + r * 8;
            float sc = scale[li0 + r * 8];
            const float* Wr = W + (size_t)gi * 4 * D_;
            float rpart = 0.f;
            #pragma unroll
            for (int nt = 0; nt < 8; nt++) {
                int gj = j0 + wn * 64 + nt * 8 + tig * 2;
                float a0 = acc[mt][nt][r * 2 + 0];
                float a1 = acc[mt][nt][r * 2 + 1];
                float2 uv = *(const float2*)(uin + (size_t)gi * D_ + gj);
                if (z == 0) {
                    float2 w1 = *(const float2*)(Wr + D_ + gj);
                    float2 w2 = *(const float2*)(Wr + 2 * D_ + gj);
                    rpart += a0 * (w1.x + uv.x * w2.x) + a1 * (w1.y + uv.y * w2.y);
                } else {
                    float2 w3 = *(const float2*)(Wr + 3 * D_ + gj);
                    rpart += a0 * uv.x * w3.x + a1 * uv.y * w3.y;
                }
            }
            part += sc * rpart;
        }
    }
    part = warp_sum(part);
    if (lane == 0) red[wid] = part;
    __syncthreads();
    if (threadIdx.x == 0) {
        float tot = 0.f;
        #pragma unroll
        for (int i = 0; i < 8; i++) tot += red[i];
        g_ctapart[z * 64 + blockIdx.y * 16 + blockIdx.x] = tot;
    }
}

// ================= final scalar =================
__global__ void ffn_final(const float* __restrict__ b, float* __restrict__ out) {
    __shared__ float red[8];
    int t = threadIdx.x;
    float s = 0.f;
    for (int i = t; i < M_; i += 256) s += g_part[i];
    if (t < 128) s += g_ctapart[t];
    s = warp_sum(s);
    if ((t & 31) == 0) red[t >> 5] = s;
    __syncthreads();
    if (t == 0) {
        float tot = 0.f;
        #pragma unroll
        for (int i = 0; i < 8; i++) tot += red[i];
        out[0] = fmaxf(tot + b[0], 0.f);
    }
}

// ================= launch =================
extern "C" void kernel_launch(void* const* d_in, const int* in_sizes, int n_in,
                              void* d_out, int out_size) {
    const float* u_p   = (const float*)d_in[0];
    const float* u_c   = (const float*)d_in[1];
    const float* w_a   = (const float*)d_in[2];
    const float* ffn_w = (const float*)d_in[3];
    const float* ffn_b = (const float*)d_in[4];
    float* out = (float*)d_out;

    cudaFuncSetAttribute(gemm_splitk,   cudaFuncAttributeMaxDynamicSharedMemorySize, SMEM_GEMM);
    cudaFuncSetAttribute(gemm_dual_ffn, cudaFuncAttributeMaxDynamicSharedMemorySize, SMEM_GEMM);

    __half *vp16, *up16, *uc16, *E16, *Sp16;
    cudaGetSymbolAddress((void**)&vp16, g_vp16);
    cudaGetSymbolAddress((void**)&up16, g_up16);
    cudaGetSymbolAddress((void**)&uc16, g_uc16);
    cudaGetSymbolAddress((void**)&E16, g_E16);
    cudaGetSymbolAddress((void**)&Sp16, g_Sp16);

    // K0: rp, rc, FFN term1, vp16, up16, uc16
    rv_kernel<<<M_ + N_, 256>>>(u_p, u_c, w_a, ffn_w);

    // GEMM1: fp16 S partials (split-K x4), then merge + E=exp(S) + rowsum
    gemm_splitk<<<dim3(N_ / 128, M_ / 256, 4), 256, SMEM_GEMM>>>(vp16, uc16, Sp16);
    merge_exp<<<M_, 256>>>();

    // column partial sums of E (combined in dual epilogue)
    col_sum<<<dim3(N_ / 128, 32), dim3(128, 4)>>>();

    // GEMM2 + GEMM3 + FFN fused (A = E / E^T, normalization in epilogue)
    gemm_dual_ffn<<<dim3(D_ / 128, M_ / 256, 2), 256, SMEM_GEMM>>>(
        E16, uc16, up16, u_p, u_c, ffn_w);

    // final scalar
    ffn_final<<<1, 256>>>(ffn_b, out);
}